// round 12
// baseline (speedup 1.0000x reference)
#include <cuda_runtime.h>
#include <cuda_fp16.h>
#include <math.h>
#include <stdint.h>

// ---------------- problem constants ----------------
#define T_TOK 2048
#define HID   2048
#define NH    32
#define NKV   8
#define HD    64
#define EPSV  1e-6f
#define SM_SCALE 0.125f

// ---------------- fp32 scratch ----------------
__device__ float g_q[T_TOK * NH * HD];     // [2048, 2048] (pre-norm QKV output)
__device__ float g_k[T_TOK * NKV * HD];    // [2048, 512]
__device__ float g_v[T_TOK * NKV * HD];    // [2048, 512]
__device__ float g_cos[T_TOK * (HD / 2)];
__device__ float g_sin[T_TOK * (HD / 2)];

// ---------------- fp16 split scratch (x = hi + lo; lo only where needed) ----
__device__ __half g_Ah[T_TOK * 4096];   // [2048,4096] = [hidden|mu] hi
__device__ __half g_Al[T_TOK * 4096];   // lo
__device__ __half g_Bh[4096 * 3072];    // fused W hi only
__device__ __half g_Oh[T_TOK * 2048];   // attention out hi/lo
__device__ __half g_Ol[T_TOK * 2048];
__device__ __half g_Wh[2048 * 2048];    // Wo hi only
// flash operands (post norm+rope)
__device__ __half g_qh[T_TOK * NH * HD];
__device__ __half g_ql[T_TOK * NH * HD];
__device__ __half g_kh[T_TOK * NKV * HD];   // hi only
__device__ __half g_vh[T_TOK * NKV * HD];   // hi only

// ============================================================================
// PTX helpers
// ============================================================================
__device__ __forceinline__ uint32_t smem_u32(const void* p) {
    return (uint32_t)__cvta_generic_to_shared(p);
}
__device__ __forceinline__ void ldsm4(uint32_t (&r)[4], uint32_t addr) {
    asm volatile("ldmatrix.sync.aligned.m8n8.x4.shared.b16 {%0,%1,%2,%3}, [%4];"
                 : "=r"(r[0]), "=r"(r[1]), "=r"(r[2]), "=r"(r[3]) : "r"(addr));
}
__device__ __forceinline__ void ldsm4t(uint32_t (&r)[4], uint32_t addr) {
    asm volatile("ldmatrix.sync.aligned.m8n8.x4.trans.shared.b16 {%0,%1,%2,%3}, [%4];"
                 : "=r"(r[0]), "=r"(r[1]), "=r"(r[2]), "=r"(r[3]) : "r"(addr));
}
__device__ __forceinline__ void mma16816(float (&c)[4], const uint32_t (&a)[4],
                                         uint32_t b0, uint32_t b1) {
    asm volatile("mma.sync.aligned.m16n8k16.row.col.f32.f16.f16.f32 "
                 "{%0,%1,%2,%3}, {%4,%5,%6,%7}, {%8,%9}, {%0,%1,%2,%3};"
                 : "+f"(c[0]), "+f"(c[1]), "+f"(c[2]), "+f"(c[3])
                 : "r"(a[0]), "r"(a[1]), "r"(a[2]), "r"(a[3]), "r"(b0), "r"(b1));
}
__device__ __forceinline__ void cpasync16(uint32_t dst, const void* src) {
    asm volatile("cp.async.cg.shared.global [%0], [%1], 16;" :: "r"(dst), "l"(src));
}
__device__ __forceinline__ void cp_commit() {
    asm volatile("cp.async.commit_group;" ::: "memory");
}
__device__ __forceinline__ void cp_wait0() {
    asm volatile("cp.async.wait_group 0;" ::: "memory");
}
__device__ __forceinline__ void cp_wait1() {
    asm volatile("cp.async.wait_group 1;" ::: "memory");
}

// ============================================================================
// fp16 split helpers/kernels
// ============================================================================
__device__ __forceinline__ uint32_t packh(__half a, __half b) {
    __half2 v = __halves2half2(a, b);
    return *reinterpret_cast<uint32_t*>(&v);
}
__device__ __forceinline__ void split_store4(__half* dh, __half* dl,
                                             size_t off, float4 x) {
    __half h0 = __float2half_rn(x.x);
    __half h1 = __float2half_rn(x.y);
    __half h2 = __float2half_rn(x.z);
    __half h3 = __float2half_rn(x.w);
    __half l0 = __float2half_rn(x.x - __half2float(h0));
    __half l1 = __float2half_rn(x.y - __half2float(h1));
    __half l2 = __float2half_rn(x.z - __half2float(h2));
    __half l3 = __float2half_rn(x.w - __half2float(h3));
    uint2 hv = {packh(h0, h1), packh(h2, h3)};
    uint2 lv = {packh(l0, l1), packh(l2, l3)};
    *reinterpret_cast<uint2*>(dh + off) = hv;
    *reinterpret_cast<uint2*>(dl + off) = lv;
}
__device__ __forceinline__ void hi_store4(__half* dh, size_t off, float4 x) {
    uint2 hv = {packh(__float2half_rn(x.x), __float2half_rn(x.y)),
                packh(__float2half_rn(x.z), __float2half_rn(x.w))};
    *reinterpret_cast<uint2*>(dh + off) = hv;
}

// A = [hidden | mu] : [2048, 4096], hi+lo
__global__ void convert_A_kernel(const float* __restrict__ hidden,
                                 const float* __restrict__ mu) {
    int idx = blockIdx.x * blockDim.x + threadIdx.x;
    if (idx >= T_TOK * 1024) return;
    int t = idx >> 10, c4 = idx & 1023;
    float4 x = (c4 < 512) ? ((const float4*)hidden)[t * 512 + c4]
                          : ((const float4*)mu)[t * 512 + c4 - 512];
    split_store4(g_Ah, g_Al, (size_t)t * 4096 + c4 * 4, x);
}

// B : [4096, 3072], hi only
__global__ void convert_B_kernel(const float* __restrict__ Wq, const float* __restrict__ Wk,
                                 const float* __restrict__ Wv, const float* __restrict__ Wmq,
                                 const float* __restrict__ Wmk, const float* __restrict__ Wmv) {
    int idx = blockIdx.x * blockDim.x + threadIdx.x;
    if (idx >= 4096 * 768) return;
    int k = idx / 768, c4 = idx % 768;
    int n = c4 * 4;
    int kk = k & 2047;
    const float* src;
    size_t off;
    if (n < 2048)      { src = (k < 2048) ? Wq : Wmq; off = (size_t)kk * 2048 + n; }
    else if (n < 2560) { src = (k < 2048) ? Wk : Wmk; off = (size_t)kk * 512 + (n - 2048); }
    else               { src = (k < 2048) ? Wv : Wmv; off = (size_t)kk * 512 + (n - 2560); }
    float4 x = *(const float4*)&src[off];
    hi_store4(g_Bh, (size_t)k * 3072 + n, x);
}

__global__ void convert_Wo_kernel(const float* __restrict__ Wo) {
    int idx = blockIdx.x * blockDim.x + threadIdx.x;
    if (idx >= 2048 * 512) return;
    float4 x = ((const float4*)Wo)[idx];
    hi_store4(g_Wh, (size_t)idx * 4, x);
}

__global__ void convert_V_kernel() {
    int idx = blockIdx.x * blockDim.x + threadIdx.x;
    if (idx >= 2048 * 128) return;
    float4 x = ((const float4*)g_v)[idx];
    hi_store4(g_vh, (size_t)idx * 4, x);
}

// ============================================================================
// Tensor-core GEMM, 2-term fp16 split (Ah·Bh + Al·Bh). Block 128x128, 8 warps,
// warp 32x64. 3-stage cp.async ring: stage s waits on loads issued at s-2.
// smem (half units): A pad-stride 40, B pad-stride 136.
// ============================================================================
#define SM_AL 15360                 // 3 * 5120
#define SM_BH 30720                 // 2 * 15360
#define SMEM_GEMM_BYTES ((30720 + 3 * 4352) * 2)   // 87552 B

__device__ __forceinline__ void gemm_core(
    const __half* __restrict__ Ah, const __half* __restrict__ Al, int lda,
    const __half* __restrict__ Bh, int ldb, int nb,
    float* __restrict__ C, int ldc, int ncBase, int kTotal)
{
    extern __shared__ __half smem[];
    __half* sAh = smem;
    __half* sAl = smem + SM_AL;
    __half* sBh = smem + SM_BH;

    const int t    = threadIdx.x;
    const int lane = t & 31;
    const int warp = t >> 5;
    const int mw   = (warp >> 1) * 32;
    const int nw   = (warp & 1) * 64;
    const int m0   = blockIdx.y * 128;

    float acc[2][8][4];
#pragma unroll
    for (int i = 0; i < 2; i++)
#pragma unroll
        for (int j = 0; j < 8; j++)
#pragma unroll
            for (int q = 0; q < 4; q++) acc[i][j][q] = 0.0f;

    auto issue = [&](int buf, int k0) {
#pragma unroll
        for (int i = 0; i < 2; i++) {
            const int c  = t + i * 256;
            const int ra = c >> 2, ca = (c & 3) * 8;
            const size_t ga = (size_t)(m0 + ra) * lda + k0 + ca;
            cpasync16(smem_u32(sAh + buf * 5120 + ra * 40 + ca), Ah + ga);
            cpasync16(smem_u32(sAl + buf * 5120 + ra * 40 + ca), Al + ga);
            const int rb = c >> 4, cb = (c & 15) * 8;
            const size_t gb = (size_t)(k0 + rb) * ldb + nb + cb;
            cpasync16(smem_u32(sBh + buf * 4352 + rb * 136 + cb), Bh + gb);
        }
        cp_commit();
    };

    const int arf = lane & 15;
    const int acf = (lane >> 4) << 3;
    const int brf = (lane & 7) + ((lane >> 3) & 1) * 8;
    const int bnf = (lane >> 4) << 3;

    const int nStages = kTotal >> 5;
    issue(0, 0);
    issue(1, 32);

    for (int s = 0; s < nStages; s++) {
        const int buf = s % 3;
        // wait for stage s's loads (issued 2 stages ago at steady state)
        if (s + 1 < nStages) cp_wait1(); else cp_wait0();
        __syncthreads();   // all warps done with compute(s-1); buffer (s+2)%3 free
        if (s + 2 < nStages) issue((s + 2) % 3, (s + 2) * 32);

        const int bufA = buf * 5120;
        const int bufB = buf * 4352;
#pragma unroll
        for (int kk = 0; kk < 2; kk++) {
            const int kc = kk * 16;
            uint32_t ah[2][4], al[2][4];
#pragma unroll
            for (int mi = 0; mi < 2; mi++) {
                int r = mw + mi * 16 + arf;
                ldsm4(ah[mi], smem_u32(sAh + bufA + r * 40 + kc + acf));
                ldsm4(al[mi], smem_u32(sAl + bufA + r * 40 + kc + acf));
            }
#pragma unroll
            for (int ng = 0; ng < 4; ng++) {
                int kr = kc + brf;
                int nc = nw + ng * 16 + bnf;
                uint32_t bh[4];
                ldsm4t(bh, smem_u32(sBh + bufB + kr * 136 + nc));
#pragma unroll
                for (int mi = 0; mi < 2; mi++) {
#pragma unroll
                    for (int nj = 0; nj < 2; nj++) {
                        mma16816(acc[mi][ng * 2 + nj], ah[mi], bh[nj * 2], bh[nj * 2 + 1]);
                        mma16816(acc[mi][ng * 2 + nj], al[mi], bh[nj * 2], bh[nj * 2 + 1]);
                    }
                }
            }
        }
    }

#pragma unroll
    for (int mi = 0; mi < 2; mi++) {
#pragma unroll
        for (int ni = 0; ni < 8; ni++) {
            int row = m0 + mw + mi * 16 + (lane >> 2);
            int col = ncBase + nw + ni * 8 + (lane & 3) * 2;
            float2 c01 = {acc[mi][ni][0], acc[mi][ni][1]};
            float2 c23 = {acc[mi][ni][2], acc[mi][ni][3]};
            *(float2*)&C[(size_t)row * ldc + col]       = c01;
            *(float2*)&C[(size_t)(row + 8) * ldc + col] = c23;
        }
    }
}

__global__ void __launch_bounds__(256) qkv_gemm_tc() {
    const int n0 = blockIdx.x * 128;
    float* C;
    int ldc, ncb;
    if (n0 < 2048)      { C = g_q; ldc = 2048; ncb = n0;        }
    else if (n0 < 2560) { C = g_k; ldc = 512;  ncb = n0 - 2048; }
    else                { C = g_v; ldc = 512;  ncb = n0 - 2560; }
    gemm_core(g_Ah, g_Al, 4096, g_Bh, 3072, n0, C, ldc, ncb, 4096);
}

__global__ void __launch_bounds__(256) out_gemm_tc(float* __restrict__ out) {
    const int n0 = blockIdx.x * 128;
    gemm_core(g_Oh, g_Ol, 2048, g_Wh, 2048, n0, out, 2048, n0, 2048);
}

// ============================================================================
// RoPE tables (double precision, tiny)
// ============================================================================
__global__ void rope_table_kernel(const int* __restrict__ positions)
{
    int idx = blockIdx.x * blockDim.x + threadIdx.x;
    if (idx >= T_TOK * 32) return;
    int t = idx >> 5;
    int i = idx & 31;
    double invf = pow(10000.0, -(double)i / 32.0);
    double fd   = (double)positions[t] * invf;
    g_cos[idx] = (float)cos(fd);
    g_sin[idx] = (float)sin(fd);
}

// ============================================================================
// Fused RMSNorm + RoPE + fp16 split (Q: hi/lo, K: hi only).
// ============================================================================
__global__ void norm_rope_kernel(const float* __restrict__ qw,
                                 const float* __restrict__ kw)
{
    int warpId = blockIdx.x * (blockDim.x >> 5) + (threadIdx.x >> 5);
    int lane   = threadIdx.x & 31;
    if (warpId >= T_TOK * (NH + NKV)) return;
    int t  = warpId / (NH + NKV);
    int hh = warpId % (NH + NKV);

    const float* buf;
    __half *dh, *dl;
    int ld, col;
    const float* w;
    if (hh < NH) { buf = g_q; dh = g_qh; dl = g_ql;    ld = NH * HD;  col = hh * HD;        w = qw; }
    else         { buf = g_k; dh = g_kh; dl = nullptr; ld = NKV * HD; col = (hh - NH) * HD; w = kw; }

    size_t o0 = (size_t)t * ld + col + lane;
    size_t o1 = o0 + 32;
    float x0 = buf[o0];
    float x1 = buf[o1];
    float ss = x0 * x0 + x1 * x1;
#pragma unroll
    for (int o = 16; o > 0; o >>= 1) ss += __shfl_xor_sync(0xffffffff, ss, o);
    float inv = rsqrtf(ss * (1.0f / 64.0f) + EPSV);
    x0 *= inv * w[lane];
    x1 *= inv * w[lane + 32];

    float c = g_cos[t * 32 + lane];
    float s = g_sin[t * 32 + lane];
    float y0 = x0 * c - x1 * s;
    float y1 = x1 * c + x0 * s;

    __half h0 = __float2half_rn(y0);
    __half h1 = __float2half_rn(y1);
    dh[o0] = h0;
    dh[o1] = h1;
    if (dl) {
        dl[o0] = __float2half_rn(y0 - __half2float(h0));
        dl[o1] = __float2half_rn(y1 - __half2float(h1));
    }
}

// ============================================================================
// Tensor-core causal flash attention, 2-term fp16:
// S = Qh·Kh + Ql·Kh ;  O += Ph·Vh + Pl·Vh.
// grid (16 q-tiles of 128, 32 heads), block 256 (8 warps);
// warp = 16 q-rows x 64 keys (per-warp fragment code unchanged).
// ============================================================================
#define FTS 72
#define FQH 0
#define FQL 9216                    // 128*72
#define FKV_BASE 18432
#define FKV_SZ 9216                 // per-buf: Kh, Vh each 64*72=4608 halfs
#define FLASH_SMEM ((FKV_BASE + 2 * FKV_SZ) * 2)   // 73728 B

__global__ void __launch_bounds__(256) flash_tc_kernel()
{
    extern __shared__ __half fsm[];
    const int qt   = blockIdx.x;
    const int h    = blockIdx.y;
    const int kvh  = h >> 2;
    const int t    = threadIdx.x;
    const int lane = t & 31;
    const int warp = t >> 5;        // 0..7
    const int mw   = warp * 16;
    const int q0   = qt * 128;

    // Q tile: 128 rows x 64 cols, hi + lo (1024 16B-chunks each)
#pragma unroll
    for (int i = 0; i < 4; i++) {
        int c = t + i * 256;
        int r = c >> 3, c8 = (c & 7) * 8;
        size_t g = (size_t)(q0 + r) * (NH * HD) + h * HD + c8;
        cpasync16(smem_u32(fsm + FQH + r * FTS + c8), g_qh + g);
        cpasync16(smem_u32(fsm + FQL + r * FTS + c8), g_ql + g);
    }
    auto issueKV = [&](int buf, int kt) {
        __half* base = fsm + FKV_BASE + buf * FKV_SZ;
#pragma unroll
        for (int i = 0; i < 2; i++) {
            int c = t + i * 256;            // 0..511
            int r = c >> 3, c8 = (c & 7) * 8;
            size_t g = (size_t)(kt * 64 + r) * (NKV * HD) + kvh * HD + c8;
            cpasync16(smem_u32(base + r * FTS + c8),        g_kh + g);
            cpasync16(smem_u32(base + 4608 + r * FTS + c8), g_vh + g);
        }
        cp_commit();
    };
    issueKV(0, 0);   // Q chunks ride in this group

    const int arf = lane & 15;
    const int acf = (lane >> 4) << 3;
    const int krow = (lane & 7) + ((lane >> 4) << 3);
    const int kcol = ((lane >> 3) & 1) << 3;
    const int vkr = (lane & 7) + ((lane >> 3) & 1) * 8;
    const int vnc = (lane >> 4) << 3;

    float mrow[2] = {-1e30f, -1e30f};
    float lrow[2] = {0.0f, 0.0f};
    float oa[8][4];
#pragma unroll
    for (int n = 0; n < 8; n++)
#pragma unroll
        for (int c = 0; c < 4; c++) oa[n][c] = 0.0f;

    uint32_t qfh[4][4], qfl[4][4];
    bool qloaded = false;

    const int nkt = 2 * qt + 2;
    int buf = 0;
    for (int kt = 0; kt < nkt; kt++) {
        if (kt + 1 < nkt) { issueKV(buf ^ 1, kt + 1); cp_wait1(); }
        else              { cp_wait0(); }
        __syncthreads();

        if (!qloaded) {
#pragma unroll
            for (int ks = 0; ks < 4; ks++) {
                ldsm4(qfh[ks], smem_u32(fsm + FQH + (mw + arf) * FTS + ks * 16 + acf));
                ldsm4(qfl[ks], smem_u32(fsm + FQL + (mw + arf) * FTS + ks * 16 + acf));
            }
            qloaded = true;
        }

        __half* sKh = fsm + FKV_BASE + buf * FKV_SZ;
        __half* sVh = sKh + 4608;

        float sc[8][4];
#pragma unroll
        for (int n = 0; n < 8; n++)
#pragma unroll
            for (int c = 0; c < 4; c++) sc[n][c] = 0.0f;

#pragma unroll
        for (int ks = 0; ks < 4; ks++) {
#pragma unroll
            for (int nt = 0; nt < 4; nt++) {
                uint32_t bh[4];
                ldsm4(bh, smem_u32(sKh + (nt * 16 + krow) * FTS + ks * 16 + kcol));
                mma16816(sc[nt * 2],     qfh[ks], bh[0], bh[1]);
                mma16816(sc[nt * 2],     qfl[ks], bh[0], bh[1]);
                mma16816(sc[nt * 2 + 1], qfh[ks], bh[2], bh[3]);
                mma16816(sc[nt * 2 + 1], qfl[ks], bh[2], bh[3]);
            }
        }

        // scale + causal mask (mask only the last two key tiles)
        const int rg0 = q0 + mw + (lane >> 2);   // global q row for c0,c1
        if (kt >= 2 * qt) {
            const int kb = kt * 64;
#pragma unroll
            for (int n = 0; n < 8; n++) {
                int cg = kb + n * 8 + (lane & 3) * 2;
                sc[n][0] = (cg     > rg0)     ? -1e30f : sc[n][0] * SM_SCALE;
                sc[n][1] = (cg + 1 > rg0)     ? -1e30f : sc[n][1] * SM_SCALE;
                sc[n][2] = (cg     > rg0 + 8) ? -1e30f : sc[n][2] * SM_SCALE;
                sc[n][3] = (cg + 1 > rg0 + 8) ? -1e30f : sc[n][3] * SM_SCALE;
            }
        } else {
#pragma unroll
            for (int n = 0; n < 8; n++)
#pragma unroll
                for (int c = 0; c < 4; c++) sc[n][c] *= SM_SCALE;
        }

        // online softmax on fragments
        float tm0 = -1e30f, tm1 = -1e30f;
#pragma unroll
        for (int n = 0; n < 8; n++) {
            tm0 = fmaxf(tm0, fmaxf(sc[n][0], sc[n][1]));
            tm1 = fmaxf(tm1, fmaxf(sc[n][2], sc[n][3]));
        }
        tm0 = fmaxf(tm0, __shfl_xor_sync(0xffffffff, tm0, 1));
        tm0 = fmaxf(tm0, __shfl_xor_sync(0xffffffff, tm0, 2));
        tm1 = fmaxf(tm1, __shfl_xor_sync(0xffffffff, tm1, 1));
        tm1 = fmaxf(tm1, __shfl_xor_sync(0xffffffff, tm1, 2));

        float mn0 = fmaxf(mrow[0], tm0);
        float mn1 = fmaxf(mrow[1], tm1);
        float al0 = __expf(mrow[0] - mn0);
        float al1 = __expf(mrow[1] - mn1);
        mrow[0] = mn0; mrow[1] = mn1;

        float sum0 = 0.0f, sum1 = 0.0f;
#pragma unroll
        for (int n = 0; n < 8; n++) {
            sc[n][0] = __expf(sc[n][0] - mn0);
            sc[n][1] = __expf(sc[n][1] - mn0);
            sc[n][2] = __expf(sc[n][2] - mn1);
            sc[n][3] = __expf(sc[n][3] - mn1);
            sum0 += sc[n][0] + sc[n][1];
            sum1 += sc[n][2] + sc[n][3];
        }
        sum0 += __shfl_xor_sync(0xffffffff, sum0, 1);
        sum0 += __shfl_xor_sync(0xffffffff, sum0, 2);
        sum1 += __shfl_xor_sync(0xffffffff, sum1, 1);
        sum1 += __shfl_xor_sync(0xffffffff, sum1, 2);
        lrow[0] = lrow[0] * al0 + sum0;
        lrow[1] = lrow[1] * al1 + sum1;

#pragma unroll
        for (int n = 0; n < 8; n++) {
            oa[n][0] *= al0; oa[n][1] *= al0;
            oa[n][2] *= al1; oa[n][3] *= al1;
        }

        // P fragments (C layout == A layout), fp16 hi/lo
        uint32_t pfh[4][4], pfl[4][4];
#pragma unroll
        for (int ks = 0; ks < 4; ks++) {
#pragma unroll
            for (int half = 0; half < 2; half++) {
                const float* pv = sc[2 * ks + half];
                __half h0 = __float2half_rn(pv[0]);
                __half h1 = __float2half_rn(pv[1]);
                __half h2 = __float2half_rn(pv[2]);
                __half h3 = __float2half_rn(pv[3]);
                pfh[ks][half * 2 + 0] = packh(h0, h1);
                pfh[ks][half * 2 + 1] = packh(h2, h3);
                pfl[ks][half * 2 + 0] = packh(__float2half_rn(pv[0] - __half2float(h0)),
                                              __float2half_rn(pv[1] - __half2float(h1)));
                pfl[ks][half * 2 + 1] = packh(__float2half_rn(pv[2] - __half2float(h2)),
                                              __float2half_rn(pv[3] - __half2float(h3)));
            }
        }

#pragma unroll
        for (int ks = 0; ks < 4; ks++) {
#pragma unroll
            for (int nt = 0; nt < 4; nt++) {
                uint32_t vh[4];
                ldsm4t(vh, smem_u32(sVh + (ks * 16 + vkr) * FTS + nt * 16 + vnc));
                mma16816(oa[nt * 2],     pfh[ks], vh[0], vh[1]);
                mma16816(oa[nt * 2],     pfl[ks], vh[0], vh[1]);
                mma16816(oa[nt * 2 + 1], pfh[ks], vh[2], vh[3]);
                mma16816(oa[nt * 2 + 1], pfl[ks], vh[2], vh[3]);
            }
        }

        __syncthreads();
        buf ^= 1;
    }

    // epilogue: normalize, split to fp16 hi/lo, store
    float inv0 = 1.0f / lrow[0];
    float inv1 = 1.0f / lrow[1];
    int row0 = q0 + mw + (lane >> 2);
#pragma unroll
    for (int n = 0; n < 8; n++) {
        int col = n * 8 + (lane & 3) * 2;
        float v0 = oa[n][0] * inv0, v1 = oa[n][1] * inv0;
        float v2 = oa[n][2] * inv1, v3 = oa[n][3] * inv1;
        size_t o0 = (size_t)row0 * (NH * HD) + h * HD + col;
        size_t o1 = (size_t)(row0 + 8) * (NH * HD) + h * HD + col;
        __half h0 = __float2half_rn(v0), h1 = __float2half_rn(v1);
        __half h2 = __float2half_rn(v2), h3 = __float2half_rn(v3);
        *(uint32_t*)&g_Oh[o0] = packh(h0, h1);
        *(uint32_t*)&g_Oh[o1] = packh(h2, h3);
        *(uint32_t*)&g_Ol[o0] = packh(__float2half_rn(v0 - __half2float(h0)),
                                      __float2half_rn(v1 - __half2float(h1)));
        *(uint32_t*)&g_Ol[o1] = packh(__float2half_rn(v2 - __half2float(h2)),
                                      __float2half_rn(v3 - __half2float(h3)));
    }
}

// ============================================================================
// launch
// ============================================================================
extern "C" void kernel_launch(void* const* d_in, const int* in_sizes, int n_in,
                              void* d_out, int out_size)
{
    const float* hidden = (const float*)d_in[0];
    const float* mu     = (const float*)d_in[1];
    const float* Wq     = (const float*)d_in[2];
    const float* Wk     = (const float*)d_in[3];
    const float* Wv     = (const float*)d_in[4];
    const float* Wo     = (const float*)d_in[5];
    const float* Wmq    = (const float*)d_in[6];
    const float* Wmk    = (const float*)d_in[7];
    const float* Wmv    = (const float*)d_in[8];
    const float* qnw    = (const float*)d_in[9];
    const float* knw    = (const float*)d_in[10];
    const int*   pos    = (const int*)d_in[11];
    float* out          = (float*)d_out;

    cudaFuncSetAttribute(qkv_gemm_tc, cudaFuncAttributeMaxDynamicSharedMemorySize, SMEM_GEMM_BYTES);
    cudaFuncSetAttribute(out_gemm_tc, cudaFuncAttributeMaxDynamicSharedMemorySize, SMEM_GEMM_BYTES);
    cudaFuncSetAttribute(flash_tc_kernel, cudaFuncAttributeMaxDynamicSharedMemorySize, FLASH_SMEM);

    // fp16 split conversions
    convert_A_kernel<<<(T_TOK * 1024 + 255) / 256, 256>>>(hidden, mu);
    convert_B_kernel<<<(4096 * 768 + 255) / 256, 256>>>(Wq, Wk, Wv, Wmq, Wmk, Wmv);
    convert_Wo_kernel<<<(2048 * 512 + 255) / 256, 256>>>(Wo);

    // QKV projection on tensor cores (fp32 out)
    qkv_gemm_tc<<<dim3(24, 16), 256, SMEM_GEMM_BYTES>>>();

    // RoPE tables + fused RMSNorm/RoPE/split
    rope_table_kernel<<<(T_TOK * 32 + 255) / 256, 256>>>(pos);
    norm_rope_kernel<<<(T_TOK * (NH + NKV) + 7) / 8, 256>>>(qnw, knw);
    convert_V_kernel<<<(2048 * 128 + 255) / 256, 256>>>();

    // tensor-core causal flash attention (128-row q tiles)
    flash_tc_kernel<<<dim3(T_TOK / 128, NH), 256, FLASH_SMEM>>>();

    // output projection on tensor cores
    out_gemm_tc<<<dim3(16, 16), 256, SMEM_GEMM_BYTES>>>(out);
}

// round 13
// speedup vs baseline: 1.1953x; 1.1953x over previous
#include <cuda_runtime.h>
#include <cuda_fp16.h>
#include <math.h>
#include <stdint.h>

// ---------------- problem constants ----------------
#define T_TOK 2048
#define HID   2048
#define NH    32
#define NKV   8
#define HD    64
#define EPSV  1e-6f
#define SM_SCALE 0.125f

// ---------------- fp32 scratch ----------------
__device__ float g_q[T_TOK * NH * HD];     // [2048, 2048] (pre-norm QKV output)
__device__ float g_k[T_TOK * NKV * HD];    // [2048, 512]
__device__ float g_v[T_TOK * NKV * HD];    // [2048, 512]
__device__ float g_cos[T_TOK * (HD / 2)];
__device__ float g_sin[T_TOK * (HD / 2)];

// ---------------- fp16 split scratch (x = hi + lo; lo only where needed) ----
__device__ __half g_Ah[T_TOK * 4096];   // [2048,4096] = [hidden|mu] hi
__device__ __half g_Al[T_TOK * 4096];   // lo
__device__ __half g_Bh[4096 * 3072];    // fused W hi only
__device__ __half g_Oh[T_TOK * 2048];   // attention out hi only
__device__ __half g_Wh[2048 * 2048];    // Wo hi only
// flash operands (post norm+rope)
__device__ __half g_qh[T_TOK * NH * HD];
__device__ __half g_ql[T_TOK * NH * HD];
__device__ __half g_kh[T_TOK * NKV * HD];   // hi only
__device__ __half g_vh[T_TOK * NKV * HD];   // hi only

// ============================================================================
// PTX helpers
// ============================================================================
__device__ __forceinline__ uint32_t smem_u32(const void* p) {
    return (uint32_t)__cvta_generic_to_shared(p);
}
__device__ __forceinline__ void ldsm4(uint32_t (&r)[4], uint32_t addr) {
    asm volatile("ldmatrix.sync.aligned.m8n8.x4.shared.b16 {%0,%1,%2,%3}, [%4];"
                 : "=r"(r[0]), "=r"(r[1]), "=r"(r[2]), "=r"(r[3]) : "r"(addr));
}
__device__ __forceinline__ void ldsm4t(uint32_t (&r)[4], uint32_t addr) {
    asm volatile("ldmatrix.sync.aligned.m8n8.x4.trans.shared.b16 {%0,%1,%2,%3}, [%4];"
                 : "=r"(r[0]), "=r"(r[1]), "=r"(r[2]), "=r"(r[3]) : "r"(addr));
}
__device__ __forceinline__ void mma16816(float (&c)[4], const uint32_t (&a)[4],
                                         uint32_t b0, uint32_t b1) {
    asm volatile("mma.sync.aligned.m16n8k16.row.col.f32.f16.f16.f32 "
                 "{%0,%1,%2,%3}, {%4,%5,%6,%7}, {%8,%9}, {%0,%1,%2,%3};"
                 : "+f"(c[0]), "+f"(c[1]), "+f"(c[2]), "+f"(c[3])
                 : "r"(a[0]), "r"(a[1]), "r"(a[2]), "r"(a[3]), "r"(b0), "r"(b1));
}
__device__ __forceinline__ void cpasync16(uint32_t dst, const void* src) {
    asm volatile("cp.async.cg.shared.global [%0], [%1], 16;" :: "r"(dst), "l"(src));
}
__device__ __forceinline__ void cp_commit() {
    asm volatile("cp.async.commit_group;" ::: "memory");
}
__device__ __forceinline__ void cp_wait0() {
    asm volatile("cp.async.wait_group 0;" ::: "memory");
}
__device__ __forceinline__ void cp_wait1() {
    asm volatile("cp.async.wait_group 1;" ::: "memory");
}

// ============================================================================
// fp16 split helpers/kernels
// ============================================================================
__device__ __forceinline__ uint32_t packh(__half a, __half b) {
    __half2 v = __halves2half2(a, b);
    return *reinterpret_cast<uint32_t*>(&v);
}
__device__ __forceinline__ void split_store4(__half* dh, __half* dl,
                                             size_t off, float4 x) {
    __half h0 = __float2half_rn(x.x);
    __half h1 = __float2half_rn(x.y);
    __half h2 = __float2half_rn(x.z);
    __half h3 = __float2half_rn(x.w);
    __half l0 = __float2half_rn(x.x - __half2float(h0));
    __half l1 = __float2half_rn(x.y - __half2float(h1));
    __half l2 = __float2half_rn(x.z - __half2float(h2));
    __half l3 = __float2half_rn(x.w - __half2float(h3));
    uint2 hv = {packh(h0, h1), packh(h2, h3)};
    uint2 lv = {packh(l0, l1), packh(l2, l3)};
    *reinterpret_cast<uint2*>(dh + off) = hv;
    *reinterpret_cast<uint2*>(dl + off) = lv;
}
__device__ __forceinline__ void hi_store4(__half* dh, size_t off, float4 x) {
    uint2 hv = {packh(__float2half_rn(x.x), __float2half_rn(x.y)),
                packh(__float2half_rn(x.z), __float2half_rn(x.w))};
    *reinterpret_cast<uint2*>(dh + off) = hv;
}

// A = [hidden | mu] : [2048, 4096], hi+lo
__global__ void convert_A_kernel(const float* __restrict__ hidden,
                                 const float* __restrict__ mu) {
    int idx = blockIdx.x * blockDim.x + threadIdx.x;
    if (idx >= T_TOK * 1024) return;
    int t = idx >> 10, c4 = idx & 1023;
    float4 x = (c4 < 512) ? ((const float4*)hidden)[t * 512 + c4]
                          : ((const float4*)mu)[t * 512 + c4 - 512];
    split_store4(g_Ah, g_Al, (size_t)t * 4096 + c4 * 4, x);
}

// B : [4096, 3072], hi only
__global__ void convert_B_kernel(const float* __restrict__ Wq, const float* __restrict__ Wk,
                                 const float* __restrict__ Wv, const float* __restrict__ Wmq,
                                 const float* __restrict__ Wmk, const float* __restrict__ Wmv) {
    int idx = blockIdx.x * blockDim.x + threadIdx.x;
    if (idx >= 4096 * 768) return;
    int k = idx / 768, c4 = idx % 768;
    int n = c4 * 4;
    int kk = k & 2047;
    const float* src;
    size_t off;
    if (n < 2048)      { src = (k < 2048) ? Wq : Wmq; off = (size_t)kk * 2048 + n; }
    else if (n < 2560) { src = (k < 2048) ? Wk : Wmk; off = (size_t)kk * 512 + (n - 2048); }
    else               { src = (k < 2048) ? Wv : Wmv; off = (size_t)kk * 512 + (n - 2560); }
    float4 x = *(const float4*)&src[off];
    hi_store4(g_Bh, (size_t)k * 3072 + n, x);
}

__global__ void convert_Wo_kernel(const float* __restrict__ Wo) {
    int idx = blockIdx.x * blockDim.x + threadIdx.x;
    if (idx >= 2048 * 512) return;
    float4 x = ((const float4*)Wo)[idx];
    hi_store4(g_Wh, (size_t)idx * 4, x);
}

__global__ void convert_V_kernel() {
    int idx = blockIdx.x * blockDim.x + threadIdx.x;
    if (idx >= 2048 * 128) return;
    float4 x = ((const float4*)g_v)[idx];
    hi_store4(g_vh, (size_t)idx * 4, x);
}

// ============================================================================
// Tensor-core GEMM. TWOA=true: D = Ah·Bh + Al·Bh (2-term fp16 split);
// TWOA=false: D = Ah·Bh. Block 128x128, 8 warps, warp 32x64,
// double-buffered cp.async (R11-verified schedule).
// smem (half units): A pad-stride 40, B pad-stride 136.
// ============================================================================
#define SM_AL 10240
#define SM_BH 20480
#define SMEM_GEMM_BYTES ((20480 + 2 * 4352) * 2)   // 58368 B

template <bool TWOA>
__device__ __forceinline__ void gemm_core(
    const __half* __restrict__ Ah, const __half* __restrict__ Al, int lda,
    const __half* __restrict__ Bh, int ldb, int nb,
    float* __restrict__ C, int ldc, int ncBase, int kTotal)
{
    extern __shared__ __half smem[];
    __half* sAh = smem;
    __half* sAl = smem + SM_AL;
    __half* sBh = smem + SM_BH;

    const int t    = threadIdx.x;
    const int lane = t & 31;
    const int warp = t >> 5;
    const int mw   = (warp >> 1) * 32;
    const int nw   = (warp & 1) * 64;
    const int m0   = blockIdx.y * 128;

    float acc[2][8][4];
#pragma unroll
    for (int i = 0; i < 2; i++)
#pragma unroll
        for (int j = 0; j < 8; j++)
#pragma unroll
            for (int q = 0; q < 4; q++) acc[i][j][q] = 0.0f;

    auto issue = [&](int buf, int k0) {
#pragma unroll
        for (int i = 0; i < 2; i++) {
            const int c  = t + i * 256;
            const int ra = c >> 2, ca = (c & 3) * 8;
            const size_t ga = (size_t)(m0 + ra) * lda + k0 + ca;
            cpasync16(smem_u32(sAh + buf * 5120 + ra * 40 + ca), Ah + ga);
            if (TWOA)
                cpasync16(smem_u32(sAl + buf * 5120 + ra * 40 + ca), Al + ga);
            const int rb = c >> 4, cb = (c & 15) * 8;
            const size_t gb = (size_t)(k0 + rb) * ldb + nb + cb;
            cpasync16(smem_u32(sBh + buf * 4352 + rb * 136 + cb), Bh + gb);
        }
        cp_commit();
    };

    const int arf = lane & 15;
    const int acf = (lane >> 4) << 3;
    const int brf = (lane & 7) + ((lane >> 3) & 1) * 8;
    const int bnf = (lane >> 4) << 3;

    issue(0, 0);
    cp_wait0();
    __syncthreads();

    const int nStages = kTotal >> 5;
    int buf = 0;
    for (int s = 0; s < nStages; s++) {
        if (s + 1 < nStages) issue(buf ^ 1, (s + 1) * 32);

        const int bufA = buf * 5120;
        const int bufB = buf * 4352;
#pragma unroll
        for (int kk = 0; kk < 2; kk++) {
            const int kc = kk * 16;
            uint32_t ah[2][4], al[2][4];
#pragma unroll
            for (int mi = 0; mi < 2; mi++) {
                int r = mw + mi * 16 + arf;
                ldsm4(ah[mi], smem_u32(sAh + bufA + r * 40 + kc + acf));
                if (TWOA)
                    ldsm4(al[mi], smem_u32(sAl + bufA + r * 40 + kc + acf));
            }
#pragma unroll
            for (int ng = 0; ng < 4; ng++) {
                int kr = kc + brf;
                int nc = nw + ng * 16 + bnf;
                uint32_t bh[4];
                ldsm4t(bh, smem_u32(sBh + bufB + kr * 136 + nc));
#pragma unroll
                for (int mi = 0; mi < 2; mi++) {
#pragma unroll
                    for (int nj = 0; nj < 2; nj++) {
                        mma16816(acc[mi][ng * 2 + nj], ah[mi], bh[nj * 2], bh[nj * 2 + 1]);
                        if (TWOA)
                            mma16816(acc[mi][ng * 2 + nj], al[mi], bh[nj * 2], bh[nj * 2 + 1]);
                    }
                }
            }
        }

        cp_wait0();
        __syncthreads();
        buf ^= 1;
    }

#pragma unroll
    for (int mi = 0; mi < 2; mi++) {
#pragma unroll
        for (int ni = 0; ni < 8; ni++) {
            int row = m0 + mw + mi * 16 + (lane >> 2);
            int col = ncBase + nw + ni * 8 + (lane & 3) * 2;
            float2 c01 = {acc[mi][ni][0], acc[mi][ni][1]};
            float2 c23 = {acc[mi][ni][2], acc[mi][ni][3]};
            *(float2*)&C[(size_t)row * ldc + col]       = c01;
            *(float2*)&C[(size_t)(row + 8) * ldc + col] = c23;
        }
    }
}

__global__ void __launch_bounds__(256) qkv_gemm_tc() {
    const int n0 = blockIdx.x * 128;
    float* C;
    int ldc, ncb;
    if (n0 < 2048)      { C = g_q; ldc = 2048; ncb = n0;        }
    else if (n0 < 2560) { C = g_k; ldc = 512;  ncb = n0 - 2048; }
    else                { C = g_v; ldc = 512;  ncb = n0 - 2560; }
    gemm_core<true>(g_Ah, g_Al, 4096, g_Bh, 3072, n0, C, ldc, ncb, 4096);
}

__global__ void __launch_bounds__(256) out_gemm_tc(float* __restrict__ out) {
    const int n0 = blockIdx.x * 128;
    gemm_core<false>(g_Oh, g_Oh, 2048, g_Wh, 2048, n0, out, 2048, n0, 2048);
}

// ============================================================================
// RoPE tables (double precision, tiny)
// ============================================================================
__global__ void rope_table_kernel(const int* __restrict__ positions)
{
    int idx = blockIdx.x * blockDim.x + threadIdx.x;
    if (idx >= T_TOK * 32) return;
    int t = idx >> 5;
    int i = idx & 31;
    double invf = pow(10000.0, -(double)i / 32.0);
    double fd   = (double)positions[t] * invf;
    g_cos[idx] = (float)cos(fd);
    g_sin[idx] = (float)sin(fd);
}

// ============================================================================
// Fused RMSNorm + RoPE + fp16 split (Q: hi/lo, K: hi only).
// ============================================================================
__global__ void norm_rope_kernel(const float* __restrict__ qw,
                                 const float* __restrict__ kw)
{
    int warpId = blockIdx.x * (blockDim.x >> 5) + (threadIdx.x >> 5);
    int lane   = threadIdx.x & 31;
    if (warpId >= T_TOK * (NH + NKV)) return;
    int t  = warpId / (NH + NKV);
    int hh = warpId % (NH + NKV);

    const float* buf;
    __half *dh, *dl;
    int ld, col;
    const float* w;
    if (hh < NH) { buf = g_q; dh = g_qh; dl = g_ql;    ld = NH * HD;  col = hh * HD;        w = qw; }
    else         { buf = g_k; dh = g_kh; dl = nullptr; ld = NKV * HD; col = (hh - NH) * HD; w = kw; }

    size_t o0 = (size_t)t * ld + col + lane;
    size_t o1 = o0 + 32;
    float x0 = buf[o0];
    float x1 = buf[o1];
    float ss = x0 * x0 + x1 * x1;
#pragma unroll
    for (int o = 16; o > 0; o >>= 1) ss += __shfl_xor_sync(0xffffffff, ss, o);
    float inv = rsqrtf(ss * (1.0f / 64.0f) + EPSV);
    x0 *= inv * w[lane];
    x1 *= inv * w[lane + 32];

    float c = g_cos[t * 32 + lane];
    float s = g_sin[t * 32 + lane];
    float y0 = x0 * c - x1 * s;
    float y1 = x1 * c + x0 * s;

    __half h0 = __float2half_rn(y0);
    __half h1 = __float2half_rn(y1);
    dh[o0] = h0;
    dh[o1] = h1;
    if (dl) {
        dl[o0] = __float2half_rn(y0 - __half2float(h0));
        dl[o1] = __float2half_rn(y1 - __half2float(h1));
    }
}

// ============================================================================
// Tensor-core causal flash attention:
// S = Qh·Kh + Ql·Kh  (2-term);  O += Ph·Vh  (1-term).
// grid (32 q-tiles of 64, 32 heads), block 128 (4 warps);
// warp = 16 q-rows x 64 keys. (R11-verified structure.)
// ============================================================================
#define FTS 72
#define FQH 0
#define FQL 4608
#define FKV_BASE 9216               // per-buf: Kh, Vh each 64*72=4608
#define FKV_SZ 9216
#define FLASH_SMEM ((FKV_BASE + 2 * FKV_SZ) * 2)   // 55296 B

__global__ void __launch_bounds__(128) flash_tc_kernel()
{
    extern __shared__ __half fsm[];
    const int qt   = blockIdx.x;
    const int h    = blockIdx.y;
    const int kvh  = h >> 2;
    const int t    = threadIdx.x;
    const int lane = t & 31;
    const int warp = t >> 5;
    const int mw   = warp * 16;
    const int q0   = qt * 64;

#pragma unroll
    for (int i = 0; i < 4; i++) {
        int c = t + i * 128;
        int r = c >> 3, c8 = (c & 7) * 8;
        size_t g = (size_t)(q0 + r) * (NH * HD) + h * HD + c8;
        cpasync16(smem_u32(fsm + FQH + r * FTS + c8), g_qh + g);
        cpasync16(smem_u32(fsm + FQL + r * FTS + c8), g_ql + g);
    }
    auto issueKV = [&](int buf, int kt) {
        __half* base = fsm + FKV_BASE + buf * FKV_SZ;
#pragma unroll
        for (int i = 0; i < 4; i++) {
            int c = t + i * 128;
            int r = c >> 3, c8 = (c & 7) * 8;
            size_t g = (size_t)(kt * 64 + r) * (NKV * HD) + kvh * HD + c8;
            cpasync16(smem_u32(base + r * FTS + c8),        g_kh + g);
            cpasync16(smem_u32(base + 4608 + r * FTS + c8), g_vh + g);
        }
        cp_commit();
    };
    issueKV(0, 0);

    const int arf = lane & 15;
    const int acf = (lane >> 4) << 3;
    const int krow = (lane & 7) + ((lane >> 4) << 3);
    const int kcol = ((lane >> 3) & 1) << 3;
    const int vkr = (lane & 7) + ((lane >> 3) & 1) * 8;
    const int vnc = (lane >> 4) << 3;

    float mrow[2] = {-1e30f, -1e30f};
    float lrow[2] = {0.0f, 0.0f};
    float oa[8][4];
#pragma unroll
    for (int n = 0; n < 8; n++)
#pragma unroll
        for (int c = 0; c < 4; c++) oa[n][c] = 0.0f;

    uint32_t qfh[4][4], qfl[4][4];
    bool qloaded = false;

    int buf = 0;
    for (int kt = 0; kt <= qt; kt++) {
        if (kt < qt) { issueKV(buf ^ 1, kt + 1); cp_wait1(); }
        else         { cp_wait0(); }
        __syncthreads();

        if (!qloaded) {
#pragma unroll
            for (int ks = 0; ks < 4; ks++) {
                ldsm4(qfh[ks], smem_u32(fsm + FQH + (mw + arf) * FTS + ks * 16 + acf));
                ldsm4(qfl[ks], smem_u32(fsm + FQL + (mw + arf) * FTS + ks * 16 + acf));
            }
            qloaded = true;
        }

        __half* sKh = fsm + FKV_BASE + buf * FKV_SZ;
        __half* sVh = sKh + 4608;

        float sc[8][4];
#pragma unroll
        for (int n = 0; n < 8; n++)
#pragma unroll
            for (int c = 0; c < 4; c++) sc[n][c] = 0.0f;

#pragma unroll
        for (int ks = 0; ks < 4; ks++) {
#pragma unroll
            for (int nt = 0; nt < 4; nt++) {
                uint32_t bh[4];
                ldsm4(bh, smem_u32(sKh + (nt * 16 + krow) * FTS + ks * 16 + kcol));
                mma16816(sc[nt * 2],     qfh[ks], bh[0], bh[1]);
                mma16816(sc[nt * 2],     qfl[ks], bh[0], bh[1]);
                mma16816(sc[nt * 2 + 1], qfh[ks], bh[2], bh[3]);
                mma16816(sc[nt * 2 + 1], qfl[ks], bh[2], bh[3]);
            }
        }

        const int rl0 = mw + (lane >> 2);
        if (kt == qt) {
#pragma unroll
            for (int n = 0; n < 8; n++) {
                int cl = n * 8 + (lane & 3) * 2;
                sc[n][0] = (cl     > rl0)     ? -1e30f : sc[n][0] * SM_SCALE;
                sc[n][1] = (cl + 1 > rl0)     ? -1e30f : sc[n][1] * SM_SCALE;
                sc[n][2] = (cl     > rl0 + 8) ? -1e30f : sc[n][2] * SM_SCALE;
                sc[n][3] = (cl + 1 > rl0 + 8) ? -1e30f : sc[n][3] * SM_SCALE;
            }
        } else {
#pragma unroll
            for (int n = 0; n < 8; n++)
#pragma unroll
                for (int c = 0; c < 4; c++) sc[n][c] *= SM_SCALE;
        }

        float tm0 = -1e30f, tm1 = -1e30f;
#pragma unroll
        for (int n = 0; n < 8; n++) {
            tm0 = fmaxf(tm0, fmaxf(sc[n][0], sc[n][1]));
            tm1 = fmaxf(tm1, fmaxf(sc[n][2], sc[n][3]));
        }
        tm0 = fmaxf(tm0, __shfl_xor_sync(0xffffffff, tm0, 1));
        tm0 = fmaxf(tm0, __shfl_xor_sync(0xffffffff, tm0, 2));
        tm1 = fmaxf(tm1, __shfl_xor_sync(0xffffffff, tm1, 1));
        tm1 = fmaxf(tm1, __shfl_xor_sync(0xffffffff, tm1, 2));

        float mn0 = fmaxf(mrow[0], tm0);
        float mn1 = fmaxf(mrow[1], tm1);
        float al0 = __expf(mrow[0] - mn0);
        float al1 = __expf(mrow[1] - mn1);
        mrow[0] = mn0; mrow[1] = mn1;

        float sum0 = 0.0f, sum1 = 0.0f;
#pragma unroll
        for (int n = 0; n < 8; n++) {
            sc[n][0] = __expf(sc[n][0] - mn0);
            sc[n][1] = __expf(sc[n][1] - mn0);
            sc[n][2] = __expf(sc[n][2] - mn1);
            sc[n][3] = __expf(sc[n][3] - mn1);
            sum0 += sc[n][0] + sc[n][1];
            sum1 += sc[n][2] + sc[n][3];
        }
        sum0 += __shfl_xor_sync(0xffffffff, sum0, 1);
        sum0 += __shfl_xor_sync(0xffffffff, sum0, 2);
        sum1 += __shfl_xor_sync(0xffffffff, sum1, 1);
        sum1 += __shfl_xor_sync(0xffffffff, sum1, 2);
        lrow[0] = lrow[0] * al0 + sum0;
        lrow[1] = lrow[1] * al1 + sum1;

#pragma unroll
        for (int n = 0; n < 8; n++) {
            oa[n][0] *= al0; oa[n][1] *= al0;
            oa[n][2] *= al1; oa[n][3] *= al1;
        }

        // P fragments (C layout == A layout), hi only
        uint32_t pfh[4][4];
#pragma unroll
        for (int ks = 0; ks < 4; ks++) {
#pragma unroll
            for (int half = 0; half < 2; half++) {
                const float* pv = sc[2 * ks + half];
                pfh[ks][half * 2 + 0] = packh(__float2half_rn(pv[0]), __float2half_rn(pv[1]));
                pfh[ks][half * 2 + 1] = packh(__float2half_rn(pv[2]), __float2half_rn(pv[3]));
            }
        }

#pragma unroll
        for (int ks = 0; ks < 4; ks++) {
#pragma unroll
            for (int nt = 0; nt < 4; nt++) {
                uint32_t vh[4];
                ldsm4t(vh, smem_u32(sVh + (ks * 16 + vkr) * FTS + nt * 16 + vnc));
                mma16816(oa[nt * 2],     pfh[ks], vh[0], vh[1]);
                mma16816(oa[nt * 2 + 1], pfh[ks], vh[2], vh[3]);
            }
        }

        __syncthreads();
        buf ^= 1;
    }

    // epilogue: normalize, store hi only (out-proj is single-term)
    float inv0 = 1.0f / lrow[0];
    float inv1 = 1.0f / lrow[1];
    int row0 = q0 + mw + (lane >> 2);
#pragma unroll
    for (int n = 0; n < 8; n++) {
        int col = n * 8 + (lane & 3) * 2;
        float v0 = oa[n][0] * inv0, v1 = oa[n][1] * inv0;
        float v2 = oa[n][2] * inv1, v3 = oa[n][3] * inv1;
        size_t o0 = (size_t)row0 * (NH * HD) + h * HD + col;
        size_t o1 = (size_t)(row0 + 8) * (NH * HD) + h * HD + col;
        *(uint32_t*)&g_Oh[o0] = packh(__float2half_rn(v0), __float2half_rn(v1));
        *(uint32_t*)&g_Oh[o1] = packh(__float2half_rn(v2), __float2half_rn(v3));
    }
}

// ============================================================================
// launch
// ============================================================================
extern "C" void kernel_launch(void* const* d_in, const int* in_sizes, int n_in,
                              void* d_out, int out_size)
{
    const float* hidden = (const float*)d_in[0];
    const float* mu     = (const float*)d_in[1];
    const float* Wq     = (const float*)d_in[2];
    const float* Wk     = (const float*)d_in[3];
    const float* Wv     = (const float*)d_in[4];
    const float* Wo     = (const float*)d_in[5];
    const float* Wmq    = (const float*)d_in[6];
    const float* Wmk    = (const float*)d_in[7];
    const float* Wmv    = (const float*)d_in[8];
    const float* qnw    = (const float*)d_in[9];
    const float* knw    = (const float*)d_in[10];
    const int*   pos    = (const int*)d_in[11];
    float* out          = (float*)d_out;

    cudaFuncSetAttribute(qkv_gemm_tc, cudaFuncAttributeMaxDynamicSharedMemorySize, SMEM_GEMM_BYTES);
    cudaFuncSetAttribute(out_gemm_tc, cudaFuncAttributeMaxDynamicSharedMemorySize, SMEM_GEMM_BYTES);
    cudaFuncSetAttribute(flash_tc_kernel, cudaFuncAttributeMaxDynamicSharedMemorySize, FLASH_SMEM);

    // fp16 split conversions
    convert_A_kernel<<<(T_TOK * 1024 + 255) / 256, 256>>>(hidden, mu);
    convert_B_kernel<<<(4096 * 768 + 255) / 256, 256>>>(Wq, Wk, Wv, Wmq, Wmk, Wmv);
    convert_Wo_kernel<<<(2048 * 512 + 255) / 256, 256>>>(Wo);

    // QKV projection on tensor cores (fp32 out)
    qkv_gemm_tc<<<dim3(24, 16), 256, SMEM_GEMM_BYTES>>>();

    // RoPE tables + fused RMSNorm/RoPE/split
    rope_table_kernel<<<(T_TOK * 32 + 255) / 256, 256>>>(pos);
    norm_rope_kernel<<<(T_TOK * (NH + NKV) + 7) / 8, 256>>>(qnw, knw);
    convert_V_kernel<<<(2048 * 128 + 255) / 256, 256>>>();

    // tensor-core causal flash attention (64-row q tiles)
    flash_tc_kernel<<<dim3(T_TOK / 64, NH), 128, FLASH_SMEM>>>();

    // output projection on tensor cores (single-term)
    out_gemm_tc<<<dim3(16, 16), 256, SMEM_GEMM_BYTES>>>(out);
}

// round 14
// speedup vs baseline: 1.4602x; 1.2216x over previous
#include <cuda_runtime.h>
#include <cuda_fp16.h>
#include <math.h>
#include <stdint.h>

// ---------------- problem constants ----------------
#define T_TOK 2048
#define HID   2048
#define NH    32
#define NKV   8
#define HD    64
#define EPSV  1e-6f
#define SM_SCALE 0.125f

// ---------------- fp32 scratch ----------------
__device__ float g_q[T_TOK * NH * HD];     // [2048, 2048] (pre-norm QKV output)
__device__ float g_k[T_TOK * NKV * HD];    // [2048, 512]
__device__ float g_v[T_TOK * NKV * HD];    // [2048, 512]
__device__ float g_cos[T_TOK * (HD / 2)];
__device__ float g_sin[T_TOK * (HD / 2)];

// ---------------- fp16 scratch (hi-only except Q) ----------------
__device__ __half g_Ah[T_TOK * 4096];   // [2048,4096] = [hidden|mu] hi only
__device__ __half g_Bh[4096 * 3072];    // fused W hi only
__device__ __half g_Oh[T_TOK * 2048];   // attention out hi only
__device__ __half g_Wh[2048 * 2048];    // Wo hi only
// flash operands (post norm+rope)
__device__ __half g_qh[T_TOK * NH * HD];
__device__ __half g_ql[T_TOK * NH * HD];    // Q keeps lo (logit sensitivity)
__device__ __half g_kh[T_TOK * NKV * HD];   // hi only
__device__ __half g_vh[T_TOK * NKV * HD];   // hi only

// ============================================================================
// PTX helpers
// ============================================================================
__device__ __forceinline__ uint32_t smem_u32(const void* p) {
    return (uint32_t)__cvta_generic_to_shared(p);
}
__device__ __forceinline__ void ldsm4(uint32_t (&r)[4], uint32_t addr) {
    asm volatile("ldmatrix.sync.aligned.m8n8.x4.shared.b16 {%0,%1,%2,%3}, [%4];"
                 : "=r"(r[0]), "=r"(r[1]), "=r"(r[2]), "=r"(r[3]) : "r"(addr));
}
__device__ __forceinline__ void ldsm4t(uint32_t (&r)[4], uint32_t addr) {
    asm volatile("ldmatrix.sync.aligned.m8n8.x4.trans.shared.b16 {%0,%1,%2,%3}, [%4];"
                 : "=r"(r[0]), "=r"(r[1]), "=r"(r[2]), "=r"(r[3]) : "r"(addr));
}
__device__ __forceinline__ void mma16816(float (&c)[4], const uint32_t (&a)[4],
                                         uint32_t b0, uint32_t b1) {
    asm volatile("mma.sync.aligned.m16n8k16.row.col.f32.f16.f16.f32 "
                 "{%0,%1,%2,%3}, {%4,%5,%6,%7}, {%8,%9}, {%0,%1,%2,%3};"
                 : "+f"(c[0]), "+f"(c[1]), "+f"(c[2]), "+f"(c[3])
                 : "r"(a[0]), "r"(a[1]), "r"(a[2]), "r"(a[3]), "r"(b0), "r"(b1));
}
__device__ __forceinline__ void cpasync16(uint32_t dst, const void* src) {
    asm volatile("cp.async.cg.shared.global [%0], [%1], 16;" :: "r"(dst), "l"(src));
}
__device__ __forceinline__ void cp_commit() {
    asm volatile("cp.async.commit_group;" ::: "memory");
}
__device__ __forceinline__ void cp_wait0() {
    asm volatile("cp.async.wait_group 0;" ::: "memory");
}
__device__ __forceinline__ void cp_wait1() {
    asm volatile("cp.async.wait_group 1;" ::: "memory");
}

// ============================================================================
// fp16 helpers/kernels
// ============================================================================
__device__ __forceinline__ uint32_t packh(__half a, __half b) {
    __half2 v = __halves2half2(a, b);
    return *reinterpret_cast<uint32_t*>(&v);
}
__device__ __forceinline__ void hi_store4(__half* dh, size_t off, float4 x) {
    uint2 hv = {packh(__float2half_rn(x.x), __float2half_rn(x.y)),
                packh(__float2half_rn(x.z), __float2half_rn(x.w))};
    *reinterpret_cast<uint2*>(dh + off) = hv;
}

// A = [hidden | mu] : [2048, 4096], hi only
__global__ void convert_A_kernel(const float* __restrict__ hidden,
                                 const float* __restrict__ mu) {
    int idx = blockIdx.x * blockDim.x + threadIdx.x;
    if (idx >= T_TOK * 1024) return;
    int t = idx >> 10, c4 = idx & 1023;
    float4 x = (c4 < 512) ? ((const float4*)hidden)[t * 512 + c4]
                          : ((const float4*)mu)[t * 512 + c4 - 512];
    hi_store4(g_Ah, (size_t)t * 4096 + c4 * 4, x);
}

// B : [4096, 3072], hi only
__global__ void convert_B_kernel(const float* __restrict__ Wq, const float* __restrict__ Wk,
                                 const float* __restrict__ Wv, const float* __restrict__ Wmq,
                                 const float* __restrict__ Wmk, const float* __restrict__ Wmv) {
    int idx = blockIdx.x * blockDim.x + threadIdx.x;
    if (idx >= 4096 * 768) return;
    int k = idx / 768, c4 = idx % 768;
    int n = c4 * 4;
    int kk = k & 2047;
    const float* src;
    size_t off;
    if (n < 2048)      { src = (k < 2048) ? Wq : Wmq; off = (size_t)kk * 2048 + n; }
    else if (n < 2560) { src = (k < 2048) ? Wk : Wmk; off = (size_t)kk * 512 + (n - 2048); }
    else               { src = (k < 2048) ? Wv : Wmv; off = (size_t)kk * 512 + (n - 2560); }
    float4 x = *(const float4*)&src[off];
    hi_store4(g_Bh, (size_t)k * 3072 + n, x);
}

__global__ void convert_Wo_kernel(const float* __restrict__ Wo) {
    int idx = blockIdx.x * blockDim.x + threadIdx.x;
    if (idx >= 2048 * 512) return;
    float4 x = ((const float4*)Wo)[idx];
    hi_store4(g_Wh, (size_t)idx * 4, x);
}

__global__ void convert_V_kernel() {
    int idx = blockIdx.x * blockDim.x + threadIdx.x;
    if (idx >= 2048 * 128) return;
    float4 x = ((const float4*)g_v)[idx];
    hi_store4(g_vh, (size_t)idx * 4, x);
}

// ============================================================================
// Tensor-core GEMM, single-term fp16 (D = Ah·Bh). Block 128x128, 8 warps,
// warp 32x64, double-buffered cp.async (verified schedule).
// smem (half units): A pad-stride 40, B pad-stride 136.
// ============================================================================
#define SM_BH 10240                 // 2 * 5120
#define SMEM_GEMM_BYTES ((10240 + 2 * 4352) * 2)   // 37888 B

__device__ __forceinline__ void gemm_core(
    const __half* __restrict__ Ah, int lda,
    const __half* __restrict__ Bh, int ldb, int nb,
    float* __restrict__ C, int ldc, int ncBase, int kTotal)
{
    extern __shared__ __half smem[];
    __half* sAh = smem;
    __half* sBh = smem + SM_BH;

    const int t    = threadIdx.x;
    const int lane = t & 31;
    const int warp = t >> 5;
    const int mw   = (warp >> 1) * 32;
    const int nw   = (warp & 1) * 64;
    const int m0   = blockIdx.y * 128;

    float acc[2][8][4];
#pragma unroll
    for (int i = 0; i < 2; i++)
#pragma unroll
        for (int j = 0; j < 8; j++)
#pragma unroll
            for (int q = 0; q < 4; q++) acc[i][j][q] = 0.0f;

    auto issue = [&](int buf, int k0) {
#pragma unroll
        for (int i = 0; i < 2; i++) {
            const int c  = t + i * 256;
            const int ra = c >> 2, ca = (c & 3) * 8;
            const size_t ga = (size_t)(m0 + ra) * lda + k0 + ca;
            cpasync16(smem_u32(sAh + buf * 5120 + ra * 40 + ca), Ah + ga);
            const int rb = c >> 4, cb = (c & 15) * 8;
            const size_t gb = (size_t)(k0 + rb) * ldb + nb + cb;
            cpasync16(smem_u32(sBh + buf * 4352 + rb * 136 + cb), Bh + gb);
        }
        cp_commit();
    };

    const int arf = lane & 15;
    const int acf = (lane >> 4) << 3;
    const int brf = (lane & 7) + ((lane >> 3) & 1) * 8;
    const int bnf = (lane >> 4) << 3;

    issue(0, 0);
    cp_wait0();
    __syncthreads();

    const int nStages = kTotal >> 5;
    int buf = 0;
    for (int s = 0; s < nStages; s++) {
        if (s + 1 < nStages) issue(buf ^ 1, (s + 1) * 32);

        const int bufA = buf * 5120;
        const int bufB = buf * 4352;
#pragma unroll
        for (int kk = 0; kk < 2; kk++) {
            const int kc = kk * 16;
            uint32_t ah[2][4];
#pragma unroll
            for (int mi = 0; mi < 2; mi++) {
                int r = mw + mi * 16 + arf;
                ldsm4(ah[mi], smem_u32(sAh + bufA + r * 40 + kc + acf));
            }
#pragma unroll
            for (int ng = 0; ng < 4; ng++) {
                int kr = kc + brf;
                int nc = nw + ng * 16 + bnf;
                uint32_t bh[4];
                ldsm4t(bh, smem_u32(sBh + bufB + kr * 136 + nc));
#pragma unroll
                for (int mi = 0; mi < 2; mi++) {
#pragma unroll
                    for (int nj = 0; nj < 2; nj++)
                        mma16816(acc[mi][ng * 2 + nj], ah[mi], bh[nj * 2], bh[nj * 2 + 1]);
                }
            }
        }

        cp_wait0();
        __syncthreads();
        buf ^= 1;
    }

#pragma unroll
    for (int mi = 0; mi < 2; mi++) {
#pragma unroll
        for (int ni = 0; ni < 8; ni++) {
            int row = m0 + mw + mi * 16 + (lane >> 2);
            int col = ncBase + nw + ni * 8 + (lane & 3) * 2;
            float2 c01 = {acc[mi][ni][0], acc[mi][ni][1]};
            float2 c23 = {acc[mi][ni][2], acc[mi][ni][3]};
            *(float2*)&C[(size_t)row * ldc + col]       = c01;
            *(float2*)&C[(size_t)(row + 8) * ldc + col] = c23;
        }
    }
}

__global__ void __launch_bounds__(256) qkv_gemm_tc() {
    const int n0 = blockIdx.x * 128;
    float* C;
    int ldc, ncb;
    if (n0 < 2048)      { C = g_q; ldc = 2048; ncb = n0;        }
    else if (n0 < 2560) { C = g_k; ldc = 512;  ncb = n0 - 2048; }
    else                { C = g_v; ldc = 512;  ncb = n0 - 2560; }
    gemm_core(g_Ah, 4096, g_Bh, 3072, n0, C, ldc, ncb, 4096);
}

__global__ void __launch_bounds__(256) out_gemm_tc(float* __restrict__ out) {
    const int n0 = blockIdx.x * 128;
    gemm_core(g_Oh, 2048, g_Wh, 2048, n0, out, 2048, n0, 2048);
}

// ============================================================================
// RoPE tables (double precision, tiny)
// ============================================================================
__global__ void rope_table_kernel(const int* __restrict__ positions)
{
    int idx = blockIdx.x * blockDim.x + threadIdx.x;
    if (idx >= T_TOK * 32) return;
    int t = idx >> 5;
    int i = idx & 31;
    double invf = pow(10000.0, -(double)i / 32.0);
    double fd   = (double)positions[t] * invf;
    g_cos[idx] = (float)cos(fd);
    g_sin[idx] = (float)sin(fd);
}

// ============================================================================
// Fused RMSNorm + RoPE + fp16 split (Q: hi/lo, K: hi only).
// ============================================================================
__global__ void norm_rope_kernel(const float* __restrict__ qw,
                                 const float* __restrict__ kw)
{
    int warpId = blockIdx.x * (blockDim.x >> 5) + (threadIdx.x >> 5);
    int lane   = threadIdx.x & 31;
    if (warpId >= T_TOK * (NH + NKV)) return;
    int t  = warpId / (NH + NKV);
    int hh = warpId % (NH + NKV);

    const float* buf;
    __half *dh, *dl;
    int ld, col;
    const float* w;
    if (hh < NH) { buf = g_q; dh = g_qh; dl = g_ql;    ld = NH * HD;  col = hh * HD;        w = qw; }
    else         { buf = g_k; dh = g_kh; dl = nullptr; ld = NKV * HD; col = (hh - NH) * HD; w = kw; }

    size_t o0 = (size_t)t * ld + col + lane;
    size_t o1 = o0 + 32;
    float x0 = buf[o0];
    float x1 = buf[o1];
    float ss = x0 * x0 + x1 * x1;
#pragma unroll
    for (int o = 16; o > 0; o >>= 1) ss += __shfl_xor_sync(0xffffffff, ss, o);
    float inv = rsqrtf(ss * (1.0f / 64.0f) + EPSV);
    x0 *= inv * w[lane];
    x1 *= inv * w[lane + 32];

    float c = g_cos[t * 32 + lane];
    float s = g_sin[t * 32 + lane];
    float y0 = x0 * c - x1 * s;
    float y1 = x1 * c + x0 * s;

    __half h0 = __float2half_rn(y0);
    __half h1 = __float2half_rn(y1);
    dh[o0] = h0;
    dh[o1] = h1;
    if (dl) {
        dl[o0] = __float2half_rn(y0 - __half2float(h0));
        dl[o1] = __float2half_rn(y1 - __half2float(h1));
    }
}

// ============================================================================
// Tensor-core causal flash attention:
// S = Qh·Kh + Ql·Kh  (2-term);  O += Ph·Vh  (1-term).
// grid (32 q-tiles of 64, 32 heads), block 128 (4 warps);
// warp = 16 q-rows x 64 keys. (Verified structure.)
// ============================================================================
#define FTS 72
#define FQH 0
#define FQL 4608
#define FKV_BASE 9216               // per-buf: Kh, Vh each 64*72=4608
#define FKV_SZ 9216
#define FLASH_SMEM ((FKV_BASE + 2 * FKV_SZ) * 2)   // 55296 B

__global__ void __launch_bounds__(128) flash_tc_kernel()
{
    extern __shared__ __half fsm[];
    const int qt   = blockIdx.x;
    const int h    = blockIdx.y;
    const int kvh  = h >> 2;
    const int t    = threadIdx.x;
    const int lane = t & 31;
    const int warp = t >> 5;
    const int mw   = warp * 16;
    const int q0   = qt * 64;

#pragma unroll
    for (int i = 0; i < 4; i++) {
        int c = t + i * 128;
        int r = c >> 3, c8 = (c & 7) * 8;
        size_t g = (size_t)(q0 + r) * (NH * HD) + h * HD + c8;
        cpasync16(smem_u32(fsm + FQH + r * FTS + c8), g_qh + g);
        cpasync16(smem_u32(fsm + FQL + r * FTS + c8), g_ql + g);
    }
    auto issueKV = [&](int buf, int kt) {
        __half* base = fsm + FKV_BASE + buf * FKV_SZ;
#pragma unroll
        for (int i = 0; i < 4; i++) {
            int c = t + i * 128;
            int r = c >> 3, c8 = (c & 7) * 8;
            size_t g = (size_t)(kt * 64 + r) * (NKV * HD) + kvh * HD + c8;
            cpasync16(smem_u32(base + r * FTS + c8),        g_kh + g);
            cpasync16(smem_u32(base + 4608 + r * FTS + c8), g_vh + g);
        }
        cp_commit();
    };
    issueKV(0, 0);

    const int arf = lane & 15;
    const int acf = (lane >> 4) << 3;
    const int krow = (lane & 7) + ((lane >> 4) << 3);
    const int kcol = ((lane >> 3) & 1) << 3;
    const int vkr = (lane & 7) + ((lane >> 3) & 1) * 8;
    const int vnc = (lane >> 4) << 3;

    float mrow[2] = {-1e30f, -1e30f};
    float lrow[2] = {0.0f, 0.0f};
    float oa[8][4];
#pragma unroll
    for (int n = 0; n < 8; n++)
#pragma unroll
        for (int c = 0; c < 4; c++) oa[n][c] = 0.0f;

    uint32_t qfh[4][4], qfl[4][4];
    bool qloaded = false;

    int buf = 0;
    for (int kt = 0; kt <= qt; kt++) {
        if (kt < qt) { issueKV(buf ^ 1, kt + 1); cp_wait1(); }
        else         { cp_wait0(); }
        __syncthreads();

        if (!qloaded) {
#pragma unroll
            for (int ks = 0; ks < 4; ks++) {
                ldsm4(qfh[ks], smem_u32(fsm + FQH + (mw + arf) * FTS + ks * 16 + acf));
                ldsm4(qfl[ks], smem_u32(fsm + FQL + (mw + arf) * FTS + ks * 16 + acf));
            }
            qloaded = true;
        }

        __half* sKh = fsm + FKV_BASE + buf * FKV_SZ;
        __half* sVh = sKh + 4608;

        float sc[8][4];
#pragma unroll
        for (int n = 0; n < 8; n++)
#pragma unroll
            for (int c = 0; c < 4; c++) sc[n][c] = 0.0f;

#pragma unroll
        for (int ks = 0; ks < 4; ks++) {
#pragma unroll
            for (int nt = 0; nt < 4; nt++) {
                uint32_t bh[4];
                ldsm4(bh, smem_u32(sKh + (nt * 16 + krow) * FTS + ks * 16 + kcol));
                mma16816(sc[nt * 2],     qfh[ks], bh[0], bh[1]);
                mma16816(sc[nt * 2],     qfl[ks], bh[0], bh[1]);
                mma16816(sc[nt * 2 + 1], qfh[ks], bh[2], bh[3]);
                mma16816(sc[nt * 2 + 1], qfl[ks], bh[2], bh[3]);
            }
        }

        const int rl0 = mw + (lane >> 2);
        if (kt == qt) {
#pragma unroll
            for (int n = 0; n < 8; n++) {
                int cl = n * 8 + (lane & 3) * 2;
                sc[n][0] = (cl     > rl0)     ? -1e30f : sc[n][0] * SM_SCALE;
                sc[n][1] = (cl + 1 > rl0)     ? -1e30f : sc[n][1] * SM_SCALE;
                sc[n][2] = (cl     > rl0 + 8) ? -1e30f : sc[n][2] * SM_SCALE;
                sc[n][3] = (cl + 1 > rl0 + 8) ? -1e30f : sc[n][3] * SM_SCALE;
            }
        } else {
#pragma unroll
            for (int n = 0; n < 8; n++)
#pragma unroll
                for (int c = 0; c < 4; c++) sc[n][c] *= SM_SCALE;
        }

        float tm0 = -1e30f, tm1 = -1e30f;
#pragma unroll
        for (int n = 0; n < 8; n++) {
            tm0 = fmaxf(tm0, fmaxf(sc[n][0], sc[n][1]));
            tm1 = fmaxf(tm1, fmaxf(sc[n][2], sc[n][3]));
        }
        tm0 = fmaxf(tm0, __shfl_xor_sync(0xffffffff, tm0, 1));
        tm0 = fmaxf(tm0, __shfl_xor_sync(0xffffffff, tm0, 2));
        tm1 = fmaxf(tm1, __shfl_xor_sync(0xffffffff, tm1, 1));
        tm1 = fmaxf(tm1, __shfl_xor_sync(0xffffffff, tm1, 2));

        float mn0 = fmaxf(mrow[0], tm0);
        float mn1 = fmaxf(mrow[1], tm1);
        float al0 = __expf(mrow[0] - mn0);
        float al1 = __expf(mrow[1] - mn1);
        mrow[0] = mn0; mrow[1] = mn1;

        float sum0 = 0.0f, sum1 = 0.0f;
#pragma unroll
        for (int n = 0; n < 8; n++) {
            sc[n][0] = __expf(sc[n][0] - mn0);
            sc[n][1] = __expf(sc[n][1] - mn0);
            sc[n][2] = __expf(sc[n][2] - mn1);
            sc[n][3] = __expf(sc[n][3] - mn1);
            sum0 += sc[n][0] + sc[n][1];
            sum1 += sc[n][2] + sc[n][3];
        }
        sum0 += __shfl_xor_sync(0xffffffff, sum0, 1);
        sum0 += __shfl_xor_sync(0xffffffff, sum0, 2);
        sum1 += __shfl_xor_sync(0xffffffff, sum1, 1);
        sum1 += __shfl_xor_sync(0xffffffff, sum1, 2);
        lrow[0] = lrow[0] * al0 + sum0;
        lrow[1] = lrow[1] * al1 + sum1;

#pragma unroll
        for (int n = 0; n < 8; n++) {
            oa[n][0] *= al0; oa[n][1] *= al0;
            oa[n][2] *= al1; oa[n][3] *= al1;
        }

        // P fragments (C layout == A layout), hi only
        uint32_t pfh[4][4];
#pragma unroll
        for (int ks = 0; ks < 4; ks++) {
#pragma unroll
            for (int half = 0; half < 2; half++) {
                const float* pv = sc[2 * ks + half];
                pfh[ks][half * 2 + 0] = packh(__float2half_rn(pv[0]), __float2half_rn(pv[1]));
                pfh[ks][half * 2 + 1] = packh(__float2half_rn(pv[2]), __float2half_rn(pv[3]));
            }
        }

#pragma unroll
        for (int ks = 0; ks < 4; ks++) {
#pragma unroll
            for (int nt = 0; nt < 4; nt++) {
                uint32_t vh[4];
                ldsm4t(vh, smem_u32(sVh + (ks * 16 + vkr) * FTS + nt * 16 + vnc));
                mma16816(oa[nt * 2],     pfh[ks], vh[0], vh[1]);
                mma16816(oa[nt * 2 + 1], pfh[ks], vh[2], vh[3]);
            }
        }

        __syncthreads();
        buf ^= 1;
    }

    // epilogue: normalize, store hi only (out-proj is single-term)
    float inv0 = 1.0f / lrow[0];
    float inv1 = 1.0f / lrow[1];
    int row0 = q0 + mw + (lane >> 2);
#pragma unroll
    for (int n = 0; n < 8; n++) {
        int col = n * 8 + (lane & 3) * 2;
        float v0 = oa[n][0] * inv0, v1 = oa[n][1] * inv0;
        float v2 = oa[n][2] * inv1, v3 = oa[n][3] * inv1;
        size_t o0 = (size_t)row0 * (NH * HD) + h * HD + col;
        size_t o1 = (size_t)(row0 + 8) * (NH * HD) + h * HD + col;
        *(uint32_t*)&g_Oh[o0] = packh(__float2half_rn(v0), __float2half_rn(v1));
        *(uint32_t*)&g_Oh[o1] = packh(__float2half_rn(v2), __float2half_rn(v3));
    }
}

// ============================================================================
// launch
// ============================================================================
extern "C" void kernel_launch(void* const* d_in, const int* in_sizes, int n_in,
                              void* d_out, int out_size)
{
    const float* hidden = (const float*)d_in[0];
    const float* mu     = (const float*)d_in[1];
    const float* Wq     = (const float*)d_in[2];
    const float* Wk     = (const float*)d_in[3];
    const float* Wv     = (const float*)d_in[4];
    const float* Wo     = (const float*)d_in[5];
    const float* Wmq    = (const float*)d_in[6];
    const float* Wmk    = (const float*)d_in[7];
    const float* Wmv    = (const float*)d_in[8];
    const float* qnw    = (const float*)d_in[9];
    const float* knw    = (const float*)d_in[10];
    const int*   pos    = (const int*)d_in[11];
    float* out          = (float*)d_out;

    cudaFuncSetAttribute(qkv_gemm_tc, cudaFuncAttributeMaxDynamicSharedMemorySize, SMEM_GEMM_BYTES);
    cudaFuncSetAttribute(out_gemm_tc, cudaFuncAttributeMaxDynamicSharedMemorySize, SMEM_GEMM_BYTES);
    cudaFuncSetAttribute(flash_tc_kernel, cudaFuncAttributeMaxDynamicSharedMemorySize, FLASH_SMEM);

    // fp16 conversions (hi only)
    convert_A_kernel<<<(T_TOK * 1024 + 255) / 256, 256>>>(hidden, mu);
    convert_B_kernel<<<(4096 * 768 + 255) / 256, 256>>>(Wq, Wk, Wv, Wmq, Wmk, Wmv);
    convert_Wo_kernel<<<(2048 * 512 + 255) / 256, 256>>>(Wo);

    // QKV projection on tensor cores (single-term, fp32 out)
    qkv_gemm_tc<<<dim3(24, 16), 256, SMEM_GEMM_BYTES>>>();

    // RoPE tables + fused RMSNorm/RoPE/split
    rope_table_kernel<<<(T_TOK * 32 + 255) / 256, 256>>>(pos);
    norm_rope_kernel<<<(T_TOK * (NH + NKV) + 7) / 8, 256>>>(qnw, knw);
    convert_V_kernel<<<(2048 * 128 + 255) / 256, 256>>>();

    // tensor-core causal flash attention
    flash_tc_kernel<<<dim3(T_TOK / 64, NH), 128, FLASH_SMEM>>>();

    // output projection on tensor cores (single-term)
    out_gemm_tc<<<dim3(16, 16), 256, SMEM_GEMM_BYTES>>>(out);
}

// round 15
// speedup vs baseline: 1.6772x; 1.1486x over previous
#include <cuda_runtime.h>
#include <cuda_fp16.h>
#include <math.h>
#include <stdint.h>

// ---------------- problem constants ----------------
#define T_TOK 2048
#define HID   2048
#define NH    32
#define NKV   8
#define HD    64
#define EPSV  1e-6f
#define SM_SCALE 0.125f

// ---------------- fp32 scratch ----------------
__device__ float g_q[T_TOK * NH * HD];     // [2048, 2048] (pre-norm QKV output)
__device__ float g_k[T_TOK * NKV * HD];    // [2048, 512]
__device__ float g_v[T_TOK * NKV * HD];    // [2048, 512]
__device__ float g_cos[T_TOK * (HD / 2)];
__device__ float g_sin[T_TOK * (HD / 2)];

// ---------------- fp16 scratch (hi-only except Q) ----------------
__device__ __half g_Ah[T_TOK * 4096];   // [2048,4096] = [hidden|mu] hi only
__device__ __half g_Bh[4096 * 3072];    // fused W hi only
__device__ __half g_Oh[T_TOK * 2048];   // attention out hi only
__device__ __half g_Wh[2048 * 2048];    // Wo hi only
// flash operands (post norm+rope)
__device__ __half g_qh[T_TOK * NH * HD];
__device__ __half g_ql[T_TOK * NH * HD];    // Q keeps lo (logit sensitivity)
__device__ __half g_kh[T_TOK * NKV * HD];   // hi only
__device__ __half g_vh[T_TOK * NKV * HD];   // hi only

// ============================================================================
// PTX helpers
// ============================================================================
__device__ __forceinline__ uint32_t smem_u32(const void* p) {
    return (uint32_t)__cvta_generic_to_shared(p);
}
__device__ __forceinline__ void ldsm4(uint32_t (&r)[4], uint32_t addr) {
    asm volatile("ldmatrix.sync.aligned.m8n8.x4.shared.b16 {%0,%1,%2,%3}, [%4];"
                 : "=r"(r[0]), "=r"(r[1]), "=r"(r[2]), "=r"(r[3]) : "r"(addr));
}
__device__ __forceinline__ void ldsm4t(uint32_t (&r)[4], uint32_t addr) {
    asm volatile("ldmatrix.sync.aligned.m8n8.x4.trans.shared.b16 {%0,%1,%2,%3}, [%4];"
                 : "=r"(r[0]), "=r"(r[1]), "=r"(r[2]), "=r"(r[3]) : "r"(addr));
}
__device__ __forceinline__ void mma16816(float (&c)[4], const uint32_t (&a)[4],
                                         uint32_t b0, uint32_t b1) {
    asm volatile("mma.sync.aligned.m16n8k16.row.col.f32.f16.f16.f32 "
                 "{%0,%1,%2,%3}, {%4,%5,%6,%7}, {%8,%9}, {%0,%1,%2,%3};"
                 : "+f"(c[0]), "+f"(c[1]), "+f"(c[2]), "+f"(c[3])
                 : "r"(a[0]), "r"(a[1]), "r"(a[2]), "r"(a[3]), "r"(b0), "r"(b1));
}
__device__ __forceinline__ void cpasync16(uint32_t dst, const void* src) {
    asm volatile("cp.async.cg.shared.global [%0], [%1], 16;" :: "r"(dst), "l"(src));
}
__device__ __forceinline__ void cp_commit() {
    asm volatile("cp.async.commit_group;" ::: "memory");
}
__device__ __forceinline__ void cp_wait0() {
    asm volatile("cp.async.wait_group 0;" ::: "memory");
}
__device__ __forceinline__ void cp_wait1() {
    asm volatile("cp.async.wait_group 1;" ::: "memory");
}
__device__ __forceinline__ void cp_wait2() {
    asm volatile("cp.async.wait_group 2;" ::: "memory");
}

// ============================================================================
// fp16 helpers/kernels
// ============================================================================
__device__ __forceinline__ uint32_t packh(__half a, __half b) {
    __half2 v = __halves2half2(a, b);
    return *reinterpret_cast<uint32_t*>(&v);
}
__device__ __forceinline__ void hi_store4(__half* dh, size_t off, float4 x) {
    uint2 hv = {packh(__float2half_rn(x.x), __float2half_rn(x.y)),
                packh(__float2half_rn(x.z), __float2half_rn(x.w))};
    *reinterpret_cast<uint2*>(dh + off) = hv;
}

// A = [hidden | mu] : [2048, 4096], hi only
__global__ void convert_A_kernel(const float* __restrict__ hidden,
                                 const float* __restrict__ mu) {
    int idx = blockIdx.x * blockDim.x + threadIdx.x;
    if (idx >= T_TOK * 1024) return;
    int t = idx >> 10, c4 = idx & 1023;
    float4 x = (c4 < 512) ? ((const float4*)hidden)[t * 512 + c4]
                          : ((const float4*)mu)[t * 512 + c4 - 512];
    hi_store4(g_Ah, (size_t)t * 4096 + c4 * 4, x);
}

// B : [4096, 3072], hi only
__global__ void convert_B_kernel(const float* __restrict__ Wq, const float* __restrict__ Wk,
                                 const float* __restrict__ Wv, const float* __restrict__ Wmq,
                                 const float* __restrict__ Wmk, const float* __restrict__ Wmv) {
    int idx = blockIdx.x * blockDim.x + threadIdx.x;
    if (idx >= 4096 * 768) return;
    int k = idx / 768, c4 = idx % 768;
    int n = c4 * 4;
    int kk = k & 2047;
    const float* src;
    size_t off;
    if (n < 2048)      { src = (k < 2048) ? Wq : Wmq; off = (size_t)kk * 2048 + n; }
    else if (n < 2560) { src = (k < 2048) ? Wk : Wmk; off = (size_t)kk * 512 + (n - 2048); }
    else               { src = (k < 2048) ? Wv : Wmv; off = (size_t)kk * 512 + (n - 2560); }
    float4 x = *(const float4*)&src[off];
    hi_store4(g_Bh, (size_t)k * 3072 + n, x);
}

__global__ void convert_Wo_kernel(const float* __restrict__ Wo) {
    int idx = blockIdx.x * blockDim.x + threadIdx.x;
    if (idx >= 2048 * 512) return;
    float4 x = ((const float4*)Wo)[idx];
    hi_store4(g_Wh, (size_t)idx * 4, x);
}

__global__ void convert_V_kernel() {
    int idx = blockIdx.x * blockDim.x + threadIdx.x;
    if (idx >= 2048 * 128) return;
    float4 x = ((const float4*)g_v)[idx];
    hi_store4(g_vh, (size_t)idx * 4, x);
}

// ============================================================================
// Tensor-core GEMM, single-term fp16 (D = Ah·Bh). Block 128x128, 8 warps,
// warp 32x64. 4-deep cp.async ring: stage s waits on group issued 3 ago
// (wait_group 2 steady state) -> 2 compute-stages of load slack.
// smem (half units): A pad-stride 40 x4 bufs, B pad-stride 136 x4 bufs.
// ============================================================================
#define SM_BH 20480                 // 4 * 5120
#define SMEM_GEMM_BYTES ((20480 + 4 * 4352) * 2)   // 75776 B

__device__ __forceinline__ void gemm_core(
    const __half* __restrict__ Ah, int lda,
    const __half* __restrict__ Bh, int ldb, int nb,
    float* __restrict__ C, int ldc, int ncBase, int kTotal)
{
    extern __shared__ __half smem[];
    __half* sAh = smem;
    __half* sBh = smem + SM_BH;

    const int t    = threadIdx.x;
    const int lane = t & 31;
    const int warp = t >> 5;
    const int mw   = (warp >> 1) * 32;
    const int nw   = (warp & 1) * 64;
    const int m0   = blockIdx.y * 128;

    float acc[2][8][4];
#pragma unroll
    for (int i = 0; i < 2; i++)
#pragma unroll
        for (int j = 0; j < 8; j++)
#pragma unroll
            for (int q = 0; q < 4; q++) acc[i][j][q] = 0.0f;

    auto issue = [&](int buf, int k0) {
#pragma unroll
        for (int i = 0; i < 2; i++) {
            const int c  = t + i * 256;
            const int ra = c >> 2, ca = (c & 3) * 8;
            const size_t ga = (size_t)(m0 + ra) * lda + k0 + ca;
            cpasync16(smem_u32(sAh + buf * 5120 + ra * 40 + ca), Ah + ga);
            const int rb = c >> 4, cb = (c & 15) * 8;
            const size_t gb = (size_t)(k0 + rb) * ldb + nb + cb;
            cpasync16(smem_u32(sBh + buf * 4352 + rb * 136 + cb), Bh + gb);
        }
        cp_commit();
    };

    const int arf = lane & 15;
    const int acf = (lane >> 4) << 3;
    const int brf = (lane & 7) + ((lane >> 3) & 1) * 8;
    const int bnf = (lane >> 4) << 3;

    const int nStages = kTotal >> 5;
    issue(0, 0);
    issue(1, 32);
    issue(2, 64);

    for (int s = 0; s < nStages; s++) {
        const int buf = s & 3;
        // wait until group s complete: allow min(2, nStages-1-s) newer pending
        const int rem = nStages - 1 - s;
        if (rem >= 2)      cp_wait2();
        else if (rem == 1) cp_wait1();
        else               cp_wait0();
        __syncthreads();   // loads visible to all; all warps past compute(s-1)

        const int bufA = buf * 5120;
        const int bufB = buf * 4352;
#pragma unroll
        for (int kk = 0; kk < 2; kk++) {
            const int kc = kk * 16;
            uint32_t ah[2][4];
#pragma unroll
            for (int mi = 0; mi < 2; mi++) {
                int r = mw + mi * 16 + arf;
                ldsm4(ah[mi], smem_u32(sAh + bufA + r * 40 + kc + acf));
            }
#pragma unroll
            for (int ng = 0; ng < 4; ng++) {
                int kr = kc + brf;
                int nc = nw + ng * 16 + bnf;
                uint32_t bh[4];
                ldsm4t(bh, smem_u32(sBh + bufB + kr * 136 + nc));
#pragma unroll
                for (int mi = 0; mi < 2; mi++) {
#pragma unroll
                    for (int nj = 0; nj < 2; nj++)
                        mma16816(acc[mi][ng * 2 + nj], ah[mi], bh[nj * 2], bh[nj * 2 + 1]);
                }
            }
        }

        // refill buffer freed by stage s-1 (all warps finished it at the sync)
        if (s + 3 < nStages) issue((s + 3) & 3, (s + 3) * 32);
    }

#pragma unroll
    for (int mi = 0; mi < 2; mi++) {
#pragma unroll
        for (int ni = 0; ni < 8; ni++) {
            int row = m0 + mw + mi * 16 + (lane >> 2);
            int col = ncBase + nw + ni * 8 + (lane & 3) * 2;
            float2 c01 = {acc[mi][ni][0], acc[mi][ni][1]};
            float2 c23 = {acc[mi][ni][2], acc[mi][ni][3]};
            *(float2*)&C[(size_t)row * ldc + col]       = c01;
            *(float2*)&C[(size_t)(row + 8) * ldc + col] = c23;
        }
    }
}

__global__ void __launch_bounds__(256) qkv_gemm_tc() {
    const int n0 = blockIdx.x * 128;
    float* C;
    int ldc, ncb;
    if (n0 < 2048)      { C = g_q; ldc = 2048; ncb = n0;        }
    else if (n0 < 2560) { C = g_k; ldc = 512;  ncb = n0 - 2048; }
    else                { C = g_v; ldc = 512;  ncb = n0 - 2560; }
    gemm_core(g_Ah, 4096, g_Bh, 3072, n0, C, ldc, ncb, 4096);
}

__global__ void __launch_bounds__(256) out_gemm_tc(float* __restrict__ out) {
    const int n0 = blockIdx.x * 128;
    gemm_core(g_Oh, 2048, g_Wh, 2048, n0, out, 2048, n0, 2048);
}

// ============================================================================
// RoPE tables (double precision, tiny)
// ============================================================================
__global__ void rope_table_kernel(const int* __restrict__ positions)
{
    int idx = blockIdx.x * blockDim.x + threadIdx.x;
    if (idx >= T_TOK * 32) return;
    int t = idx >> 5;
    int i = idx & 31;
    double invf = pow(10000.0, -(double)i / 32.0);
    double fd   = (double)positions[t] * invf;
    g_cos[idx] = (float)cos(fd);
    g_sin[idx] = (float)sin(fd);
}

// ============================================================================
// Fused RMSNorm + RoPE + fp16 split (Q: hi/lo, K: hi only).
// ============================================================================
__global__ void norm_rope_kernel(const float* __restrict__ qw,
                                 const float* __restrict__ kw)
{
    int warpId = blockIdx.x * (blockDim.x >> 5) + (threadIdx.x >> 5);
    int lane   = threadIdx.x & 31;
    if (warpId >= T_TOK * (NH + NKV)) return;
    int t  = warpId / (NH + NKV);
    int hh = warpId % (NH + NKV);

    const float* buf;
    __half *dh, *dl;
    int ld, col;
    const float* w;
    if (hh < NH) { buf = g_q; dh = g_qh; dl = g_ql;    ld = NH * HD;  col = hh * HD;        w = qw; }
    else         { buf = g_k; dh = g_kh; dl = nullptr; ld = NKV * HD; col = (hh - NH) * HD; w = kw; }

    size_t o0 = (size_t)t * ld + col + lane;
    size_t o1 = o0 + 32;
    float x0 = buf[o0];
    float x1 = buf[o1];
    float ss = x0 * x0 + x1 * x1;
#pragma unroll
    for (int o = 16; o > 0; o >>= 1) ss += __shfl_xor_sync(0xffffffff, ss, o);
    float inv = rsqrtf(ss * (1.0f / 64.0f) + EPSV);
    x0 *= inv * w[lane];
    x1 *= inv * w[lane + 32];

    float c = g_cos[t * 32 + lane];
    float s = g_sin[t * 32 + lane];
    float y0 = x0 * c - x1 * s;
    float y1 = x1 * c + x0 * s;

    __half h0 = __float2half_rn(y0);
    __half h1 = __float2half_rn(y1);
    dh[o0] = h0;
    dh[o1] = h1;
    if (dl) {
        dl[o0] = __float2half_rn(y0 - __half2float(h0));
        dl[o1] = __float2half_rn(y1 - __half2float(h1));
    }
}

// ============================================================================
// Tensor-core causal flash attention:
// S = Qh·Kh + Ql·Kh  (2-term);  O += Ph·Vh  (1-term).
// grid (32 q-tiles of 64, 32 heads), block 128 (4 warps);
// warp = 16 q-rows x 64 keys. (Verified structure.)
// ============================================================================
#define FTS 72
#define FQH 0
#define FQL 4608
#define FKV_BASE 9216               // per-buf: Kh, Vh each 64*72=4608
#define FKV_SZ 9216
#define FLASH_SMEM ((FKV_BASE + 2 * FKV_SZ) * 2)   // 55296 B

__global__ void __launch_bounds__(128) flash_tc_kernel()
{
    extern __shared__ __half fsm[];
    const int qt   = blockIdx.x;
    const int h    = blockIdx.y;
    const int kvh  = h >> 2;
    const int t    = threadIdx.x;
    const int lane = t & 31;
    const int warp = t >> 5;
    const int mw   = warp * 16;
    const int q0   = qt * 64;

#pragma unroll
    for (int i = 0; i < 4; i++) {
        int c = t + i * 128;
        int r = c >> 3, c8 = (c & 7) * 8;
        size_t g = (size_t)(q0 + r) * (NH * HD) + h * HD + c8;
        cpasync16(smem_u32(fsm + FQH + r * FTS + c8), g_qh + g);
        cpasync16(smem_u32(fsm + FQL + r * FTS + c8), g_ql + g);
    }
    auto issueKV = [&](int buf, int kt) {
        __half* base = fsm + FKV_BASE + buf * FKV_SZ;
#pragma unroll
        for (int i = 0; i < 4; i++) {
            int c = t + i * 128;
            int r = c >> 3, c8 = (c & 7) * 8;
            size_t g = (size_t)(kt * 64 + r) * (NKV * HD) + kvh * HD + c8;
            cpasync16(smem_u32(base + r * FTS + c8),        g_kh + g);
            cpasync16(smem_u32(base + 4608 + r * FTS + c8), g_vh + g);
        }
        cp_commit();
    };
    issueKV(0, 0);

    const int arf = lane & 15;
    const int acf = (lane >> 4) << 3;
    const int krow = (lane & 7) + ((lane >> 4) << 3);
    const int kcol = ((lane >> 3) & 1) << 3;
    const int vkr = (lane & 7) + ((lane >> 3) & 1) * 8;
    const int vnc = (lane >> 4) << 3;

    float mrow[2] = {-1e30f, -1e30f};
    float lrow[2] = {0.0f, 0.0f};
    float oa[8][4];
#pragma unroll
    for (int n = 0; n < 8; n++)
#pragma unroll
        for (int c = 0; c < 4; c++) oa[n][c] = 0.0f;

    uint32_t qfh[4][4], qfl[4][4];
    bool qloaded = false;

    int buf = 0;
    for (int kt = 0; kt <= qt; kt++) {
        if (kt < qt) { issueKV(buf ^ 1, kt + 1); cp_wait1(); }
        else         { cp_wait0(); }
        __syncthreads();

        if (!qloaded) {
#pragma unroll
            for (int ks = 0; ks < 4; ks++) {
                ldsm4(qfh[ks], smem_u32(fsm + FQH + (mw + arf) * FTS + ks * 16 + acf));
                ldsm4(qfl[ks], smem_u32(fsm + FQL + (mw + arf) * FTS + ks * 16 + acf));
            }
            qloaded = true;
        }

        __half* sKh = fsm + FKV_BASE + buf * FKV_SZ;
        __half* sVh = sKh + 4608;

        float sc[8][4];
#pragma unroll
        for (int n = 0; n < 8; n++)
#pragma unroll
            for (int c = 0; c < 4; c++) sc[n][c] = 0.0f;

#pragma unroll
        for (int ks = 0; ks < 4; ks++) {
#pragma unroll
            for (int nt = 0; nt < 4; nt++) {
                uint32_t bh[4];
                ldsm4(bh, smem_u32(sKh + (nt * 16 + krow) * FTS + ks * 16 + kcol));
                mma16816(sc[nt * 2],     qfh[ks], bh[0], bh[1]);
                mma16816(sc[nt * 2],     qfl[ks], bh[0], bh[1]);
                mma16816(sc[nt * 2 + 1], qfh[ks], bh[2], bh[3]);
                mma16816(sc[nt * 2 + 1], qfl[ks], bh[2], bh[3]);
            }
        }

        const int rl0 = mw + (lane >> 2);
        if (kt == qt) {
#pragma unroll
            for (int n = 0; n < 8; n++) {
                int cl = n * 8 + (lane & 3) * 2;
                sc[n][0] = (cl     > rl0)     ? -1e30f : sc[n][0] * SM_SCALE;
                sc[n][1] = (cl + 1 > rl0)     ? -1e30f : sc[n][1] * SM_SCALE;
                sc[n][2] = (cl     > rl0 + 8) ? -1e30f : sc[n][2] * SM_SCALE;
                sc[n][3] = (cl + 1 > rl0 + 8) ? -1e30f : sc[n][3] * SM_SCALE;
            }
        } else {
#pragma unroll
            for (int n = 0; n < 8; n++)
#pragma unroll
                for (int c = 0; c < 4; c++) sc[n][c] *= SM_SCALE;
        }

        float tm0 = -1e30f, tm1 = -1e30f;
#pragma unroll
        for (int n = 0; n < 8; n++) {
            tm0 = fmaxf(tm0, fmaxf(sc[n][0], sc[n][1]));
            tm1 = fmaxf(tm1, fmaxf(sc[n][2], sc[n][3]));
        }
        tm0 = fmaxf(tm0, __shfl_xor_sync(0xffffffff, tm0, 1));
        tm0 = fmaxf(tm0, __shfl_xor_sync(0xffffffff, tm0, 2));
        tm1 = fmaxf(tm1, __shfl_xor_sync(0xffffffff, tm1, 1));
        tm1 = fmaxf(tm1, __shfl_xor_sync(0xffffffff, tm1, 2));

        float mn0 = fmaxf(mrow[0], tm0);
        float mn1 = fmaxf(mrow[1], tm1);
        float al0 = __expf(mrow[0] - mn0);
        float al1 = __expf(mrow[1] - mn1);
        mrow[0] = mn0; mrow[1] = mn1;

        float sum0 = 0.0f, sum1 = 0.0f;
#pragma unroll
        for (int n = 0; n < 8; n++) {
            sc[n][0] = __expf(sc[n][0] - mn0);
            sc[n][1] = __expf(sc[n][1] - mn0);
            sc[n][2] = __expf(sc[n][2] - mn1);
            sc[n][3] = __expf(sc[n][3] - mn1);
            sum0 += sc[n][0] + sc[n][1];
            sum1 += sc[n][2] + sc[n][3];
        }
        sum0 += __shfl_xor_sync(0xffffffff, sum0, 1);
        sum0 += __shfl_xor_sync(0xffffffff, sum0, 2);
        sum1 += __shfl_xor_sync(0xffffffff, sum1, 1);
        sum1 += __shfl_xor_sync(0xffffffff, sum1, 2);
        lrow[0] = lrow[0] * al0 + sum0;
        lrow[1] = lrow[1] * al1 + sum1;

#pragma unroll
        for (int n = 0; n < 8; n++) {
            oa[n][0] *= al0; oa[n][1] *= al0;
            oa[n][2] *= al1; oa[n][3] *= al1;
        }

        // P fragments (C layout == A layout), hi only
        uint32_t pfh[4][4];
#pragma unroll
        for (int ks = 0; ks < 4; ks++) {
#pragma unroll
            for (int half = 0; half < 2; half++) {
                const float* pv = sc[2 * ks + half];
                pfh[ks][half * 2 + 0] = packh(__float2half_rn(pv[0]), __float2half_rn(pv[1]));
                pfh[ks][half * 2 + 1] = packh(__float2half_rn(pv[2]), __float2half_rn(pv[3]));
            }
        }

#pragma unroll
        for (int ks = 0; ks < 4; ks++) {
#pragma unroll
            for (int nt = 0; nt < 4; nt++) {
                uint32_t vh[4];
                ldsm4t(vh, smem_u32(sVh + (ks * 16 + vkr) * FTS + nt * 16 + vnc));
                mma16816(oa[nt * 2],     pfh[ks], vh[0], vh[1]);
                mma16816(oa[nt * 2 + 1], pfh[ks], vh[2], vh[3]);
            }
        }

        __syncthreads();
        buf ^= 1;
    }

    // epilogue: normalize, store hi only (out-proj is single-term)
    float inv0 = 1.0f / lrow[0];
    float inv1 = 1.0f / lrow[1];
    int row0 = q0 + mw + (lane >> 2);
#pragma unroll
    for (int n = 0; n < 8; n++) {
        int col = n * 8 + (lane & 3) * 2;
        float v0 = oa[n][0] * inv0, v1 = oa[n][1] * inv0;
        float v2 = oa[n][2] * inv1, v3 = oa[n][3] * inv1;
        size_t o0 = (size_t)row0 * (NH * HD) + h * HD + col;
        size_t o1 = (size_t)(row0 + 8) * (NH * HD) + h * HD + col;
        *(uint32_t*)&g_Oh[o0] = packh(__float2half_rn(v0), __float2half_rn(v1));
        *(uint32_t*)&g_Oh[o1] = packh(__float2half_rn(v2), __float2half_rn(v3));
    }
}

// ============================================================================
// launch
// ============================================================================
extern "C" void kernel_launch(void* const* d_in, const int* in_sizes, int n_in,
                              void* d_out, int out_size)
{
    const float* hidden = (const float*)d_in[0];
    const float* mu     = (const float*)d_in[1];
    const float* Wq     = (const float*)d_in[2];
    const float* Wk     = (const float*)d_in[3];
    const float* Wv     = (const float*)d_in[4];
    const float* Wo     = (const float*)d_in[5];
    const float* Wmq    = (const float*)d_in[6];
    const float* Wmk    = (const float*)d_in[7];
    const float* Wmv    = (const float*)d_in[8];
    const float* qnw    = (const float*)d_in[9];
    const float* knw    = (const float*)d_in[10];
    const int*   pos    = (const int*)d_in[11];
    float* out          = (float*)d_out;

    cudaFuncSetAttribute(qkv_gemm_tc, cudaFuncAttributeMaxDynamicSharedMemorySize, SMEM_GEMM_BYTES);
    cudaFuncSetAttribute(out_gemm_tc, cudaFuncAttributeMaxDynamicSharedMemorySize, SMEM_GEMM_BYTES);
    cudaFuncSetAttribute(flash_tc_kernel, cudaFuncAttributeMaxDynamicSharedMemorySize, FLASH_SMEM);

    // fp16 conversions (hi only)
    convert_A_kernel<<<(T_TOK * 1024 + 255) / 256, 256>>>(hidden, mu);
    convert_B_kernel<<<(4096 * 768 + 255) / 256, 256>>>(Wq, Wk, Wv, Wmq, Wmk, Wmv);
    convert_Wo_kernel<<<(2048 * 512 + 255) / 256, 256>>>(Wo);

    // QKV projection on tensor cores (single-term, fp32 out)
    qkv_gemm_tc<<<dim3(24, 16), 256, SMEM_GEMM_BYTES>>>();

    // RoPE tables + fused RMSNorm/RoPE/split
    rope_table_kernel<<<(T_TOK * 32 + 255) / 256, 256>>>(pos);
    norm_rope_kernel<<<(T_TOK * (NH + NKV) + 7) / 8, 256>>>(qnw, knw);
    convert_V_kernel<<<(2048 * 128 + 255) / 256, 256>>>();

    // tensor-core causal flash attention
    flash_tc_kernel<<<dim3(T_TOK / 64, NH), 128, FLASH_SMEM>>>();

    // output projection on tensor cores (single-term)
    out_gemm_tc<<<dim3(16, 16), 256, SMEM_GEMM_BYTES>>>(out);
}